// round 1
// baseline (speedup 1.0000x reference)
#include <cuda_runtime.h>

#define B_  4
#define C_  256
#define NH_ 4
#define D_  64
#define T_  1024
#define EPS_ 1e-5f

// ------------------------- static scratch (no allocs) -------------------------
__device__ float g_wt[3][C_ * C_];          // transposed wq/wk/wv  [c][o]
__device__ float g_q[B_][C_ * T_];
__device__ float g_k[B_][C_ * T_];
__device__ float g_v[B_][C_ * T_];
__device__ float g_s[B_ * NH_][T_ * T_];    // raw per-head scores (scaled)
__device__ float g_a[B_ * NH_][T_ * T_];    // softmax(mixed scores)
__device__ float g_rowsq[B_ * NH_][T_];     // per-row sum(a^2)
__device__ float g_ssq[B_ * NH_];           // total sum(a^2) per (b,g)
__device__ float g_vsum[B_][C_];            // sum over t of v
__device__ float g_x2[B_][T_ * C_];         // reshaped attention output [t'][c']

// ------------------------- reductions -------------------------
__device__ __forceinline__ float blkReduceSum(float v, float* red) {
    #pragma unroll
    for (int o = 16; o > 0; o >>= 1) v += __shfl_xor_sync(0xffffffffu, v, o);
    if ((threadIdx.x & 31) == 0) red[threadIdx.x >> 5] = v;
    __syncthreads();
    float s = red[0];
    #pragma unroll
    for (int i = 1; i < 8; i++) s += red[i];
    __syncthreads();
    return s;
}

__device__ __forceinline__ float blkReduceMax(float v, float* red) {
    #pragma unroll
    for (int o = 16; o > 0; o >>= 1) v = fmaxf(v, __shfl_xor_sync(0xffffffffu, v, o));
    if ((threadIdx.x & 31) == 0) red[threadIdx.x >> 5] = v;
    __syncthreads();
    float s = red[0];
    #pragma unroll
    for (int i = 1; i < 8; i++) s = fmaxf(s, red[i]);
    __syncthreads();
    return s;
}

// ------------------------- weight transpose -------------------------
__global__ void k_transpose(const float* __restrict__ wq,
                            const float* __restrict__ wk,
                            const float* __restrict__ wv) {
    __shared__ float tile[32][33];
    const float* src = (blockIdx.z == 0) ? wq : ((blockIdx.z == 1) ? wk : wv);
    int c = blockIdx.x * 32 + threadIdx.x;
    int o = blockIdx.y * 32 + threadIdx.y;
    tile[threadIdx.y][threadIdx.x] = src[o * C_ + c];
    __syncthreads();
    int oo = blockIdx.y * 32 + threadIdx.x;
    int cc = blockIdx.x * 32 + threadIdx.y;
    g_wt[blockIdx.z][cc * C_ + oo] = tile[threadIdx.x][threadIdx.y];
}

// ------------------------- TN GEMM body: C[m,n] = alpha * sum_k A[k,m]*B[k,n] -------------------------
// 64x64 tile, BK=16, 256 threads, 4x4 per thread.
__device__ __forceinline__ void gemm_tn_body(
    const float* __restrict__ A, int lda,
    const float* __restrict__ B, int ldb,
    float* __restrict__ C, int ldc,
    int K, float alpha, int m0, int n0) {
    __shared__ float As[16][64];
    __shared__ float Bs[16][64];
    float acc[4][4] = {};
    const int tid = threadIdx.x;
    const int lm = tid & 63;
    const int lk = tid >> 6;      // 0..3
    const int ty = tid >> 4;      // 0..15
    const int tx = tid & 15;
    for (int k0 = 0; k0 < K; k0 += 16) {
        #pragma unroll
        for (int p = 0; p < 4; p++) {
            int kk = lk + p * 4;
            As[kk][lm] = A[(k0 + kk) * lda + m0 + lm];
            Bs[kk][lm] = B[(k0 + kk) * ldb + n0 + lm];
        }
        __syncthreads();
        #pragma unroll
        for (int k = 0; k < 16; k++) {
            float4 a4 = *(const float4*)&As[k][ty * 4];
            float4 b4 = *(const float4*)&Bs[k][tx * 4];
            float av[4] = {a4.x, a4.y, a4.z, a4.w};
            float bv[4] = {b4.x, b4.y, b4.z, b4.w};
            #pragma unroll
            for (int i = 0; i < 4; i++)
                #pragma unroll
                for (int j = 0; j < 4; j++)
                    acc[i][j] += av[i] * bv[j];
        }
        __syncthreads();
    }
    #pragma unroll
    for (int i = 0; i < 4; i++) {
        int m = m0 + ty * 4 + i;
        #pragma unroll
        for (int j = 0; j < 4; j++)
            C[m * ldc + n0 + tx * 4 + j] = alpha * acc[i][j];
    }
}

// K1: q/k/v = Wt^T x  -> grid (16, 4, 12)  z = w*4 + b
__global__ void __launch_bounds__(256) k_qkv(const float* __restrict__ x) {
    int z = blockIdx.z;
    int w = z >> 2, b = z & 3;
    float* C = (w == 0) ? g_q[b] : ((w == 1) ? g_k[b] : g_v[b]);
    gemm_tn_body(g_wt[w], C_, x + (size_t)b * C_ * T_, T_, C, T_, C_, 1.0f,
                 blockIdx.y * 64, blockIdx.x * 64);
}

// K2: per-head scores s[q,t] = scale * sum_d q[d,q] k[d,t] -> grid (16,16,16)
__global__ void __launch_bounds__(256) k_score() {
    int z = blockIdx.z;
    int b = z >> 2, h = z & 3;
    gemm_tn_body(g_q[b] + h * D_ * T_, T_, g_k[b] + h * D_ * T_, T_,
                 g_s[z], T_, D_, 0.125f, blockIdx.y * 64, blockIdx.x * 64);
}

// vsum[b][c] = sum_t v[b][c][t]   -> grid (B*C), 256 thr
__global__ void k_vsum() {
    __shared__ float red[8];
    int b = blockIdx.x >> 8, c = blockIdx.x & 255;
    const float* row = g_v[b] + c * T_;
    float s = 0.f;
    for (int i = threadIdx.x; i < T_; i += 256) s += row[i];
    s = blkReduceSum(s, red);
    if (threadIdx.x == 0) g_vsum[b][c] = s;
}

// K3: head-mix + softmax + per-row sum(a^2). grid (B*T), 256 thr
__global__ void __launch_bounds__(256) k_softmax(const float* __restrict__ w_head) {
    __shared__ float rows[NH_][T_];
    __shared__ float red[8];
    int b = blockIdx.x >> 10, qq = blockIdx.x & 1023;
    const int tid = threadIdx.x;

    #pragma unroll
    for (int h = 0; h < NH_; h++)
        for (int i = tid; i < T_; i += 256)
            rows[h][i] = g_s[b * NH_ + h][qq * T_ + i];
    __syncthreads();

    float wh[NH_][NH_];
    #pragma unroll
    for (int g = 0; g < NH_; g++)
        #pragma unroll
        for (int h = 0; h < NH_; h++)
            wh[g][h] = w_head[g * NH_ + h];

    for (int g = 0; g < NH_; g++) {
        float m[4];
        float mx = -3.4e38f;
        #pragma unroll
        for (int j = 0; j < 4; j++) {
            int t = tid + j * 256;
            float v = wh[g][0] * rows[0][t] + wh[g][1] * rows[1][t]
                    + wh[g][2] * rows[2][t] + wh[g][3] * rows[3][t];
            m[j] = v;
            mx = fmaxf(mx, v);
        }
        mx = blkReduceMax(mx, red);
        float e[4], s = 0.f;
        #pragma unroll
        for (int j = 0; j < 4; j++) { e[j] = __expf(m[j] - mx); s += e[j]; }
        s = blkReduceSum(s, red);
        float inv = 1.0f / s;
        float sq = 0.f;
        float* arow = g_a[b * NH_ + g] + qq * T_;
        #pragma unroll
        for (int j = 0; j < 4; j++) {
            float av = e[j] * inv;
            arow[tid + j * 256] = av;
            sq += av * av;
        }
        sq = blkReduceSum(sq, red);
        if (tid == 0) g_rowsq[b * NH_ + g][qq] = sq;
        __syncthreads();
    }
}

// reduce rowsq -> ssq (deterministic). grid (16), 256 thr
__global__ void k_ssq() {
    __shared__ float red[8];
    int g = blockIdx.x;
    float s = 0.f;
    for (int i = threadIdx.x; i < T_; i += 256) s += g_rowsq[g][i];
    s = blkReduceSum(s, red);
    if (threadIdx.x == 0) g_ssq[g] = s;
}

// K4: NT GEMM out[q,d] = sum_t a[q,t] v[d,t], fold instance-norm, scatter-reshape.
// BM=32, BN=64(all of d), BK=16. grid (1, 32, 16), 256 thr, 2x4 per thread.
__global__ void __launch_bounds__(256) k_av(const float* __restrict__ gamma,
                                            const float* __restrict__ beta) {
    int z = blockIdx.z;
    int b = z >> 2, h = z & 3;
    const float* A  = g_a[z];                  // [q][t]
    const float* Bv = g_v[b] + h * D_ * T_;    // [d][t]
    int m0 = blockIdx.y * 32;
    __shared__ float Ast[16][34];   // [k][m], stride keeps float2 aligned, conflict-free store
    __shared__ float Bst[16][68];   // [k][n], stride keeps float4 aligned
    float acc[2][4] = {};
    const int tid = threadIdx.x;
    const int lk = tid & 15, lr = tid >> 4;    // loader coords
    const int ty = tid >> 4, tx = tid & 15;    // compute coords
    for (int k0 = 0; k0 < T_; k0 += 16) {
        #pragma unroll
        for (int p = 0; p < 2; p++)
            Ast[lk][lr + p * 16] = A[(m0 + lr + p * 16) * T_ + k0 + lk];
        #pragma unroll
        for (int p = 0; p < 4; p++)
            Bst[lk][lr + p * 16] = Bv[(lr + p * 16) * T_ + k0 + lk];
        __syncthreads();
        #pragma unroll
        for (int k = 0; k < 16; k++) {
            float2 a2 = *(const float2*)&Ast[k][ty * 2];
            float4 b4 = *(const float4*)&Bst[k][tx * 4];
            acc[0][0] += a2.x * b4.x;  acc[0][1] += a2.x * b4.y;
            acc[0][2] += a2.x * b4.z;  acc[0][3] += a2.x * b4.w;
            acc[1][0] += a2.y * b4.x;  acc[1][1] += a2.y * b4.y;
            acc[1][2] += a2.y * b4.z;  acc[1][3] += a2.y * b4.w;
        }
        __syncthreads();
    }
    // fold InstanceNorm: mean is exactly 1/T, var = ssq/T^2 - mu^2
    const float mu  = 1.0f / (float)T_;
    const float var = g_ssq[z] * (1.0f / ((float)T_ * (float)T_)) - mu * mu;
    const float invs = rsqrtf(var + EPS_);
    const float c1 = gamma[h] * invs;
    const float c0 = beta[h] - c1 * mu;
    #pragma unroll
    for (int i = 0; i < 2; i++) {
        int q = m0 + ty * 2 + i;
        int xrow  = h * 256 + (q >> 2);     // t'
        int cbase = (q & 3) * 64;           // c' base
        #pragma unroll
        for (int j = 0; j < 4; j++) {
            int d = tx * 4 + j;
            g_x2[b][xrow * C_ + cbase + d] =
                c1 * acc[i][j] + c0 * g_vsum[b][h * D_ + d];
        }
    }
}

// K5: NT GEMM  y[o,t'] = sum_c wp[o,c] * X[t',c] + bias[o]   -> d_out [b][o][t']
// 64x64 tile, BK=16, grid (16, 4, 4)
__global__ void __launch_bounds__(256) k_proj(const float* __restrict__ wp,
                                              const float* __restrict__ bp,
                                              float* __restrict__ out) {
    int b = blockIdx.z;
    int m0 = blockIdx.y * 64;   // o
    int n0 = blockIdx.x * 64;   // t'
    __shared__ float Ast[16][68];
    __shared__ float Bst[16][68];
    float acc[4][4] = {};
    const int tid = threadIdx.x;
    const int lk = tid & 15, lr = tid >> 4;
    const int ty = tid >> 4, tx = tid & 15;
    const float* X = g_x2[b];
    for (int k0 = 0; k0 < C_; k0 += 16) {
        #pragma unroll
        for (int p = 0; p < 4; p++) {
            Ast[lk][lr + p * 16] = wp[(m0 + lr + p * 16) * C_ + k0 + lk];
            Bst[lk][lr + p * 16] = X[(n0 + lr + p * 16) * C_ + k0 + lk];
        }
        __syncthreads();
        #pragma unroll
        for (int k = 0; k < 16; k++) {
            float4 a4 = *(const float4*)&Ast[k][ty * 4];
            float4 b4 = *(const float4*)&Bst[k][tx * 4];
            float av[4] = {a4.x, a4.y, a4.z, a4.w};
            float bv[4] = {b4.x, b4.y, b4.z, b4.w};
            #pragma unroll
            for (int i = 0; i < 4; i++)
                #pragma unroll
                for (int j = 0; j < 4; j++)
                    acc[i][j] += av[i] * bv[j];
        }
        __syncthreads();
    }
    #pragma unroll
    for (int i = 0; i < 4; i++) {
        int o = m0 + ty * 4 + i;
        float bias = bp[o];
        #pragma unroll
        for (int j = 0; j < 4; j++)
            out[(size_t)b * C_ * T_ + o * T_ + n0 + tx * 4 + j] = acc[i][j] + bias;
    }
}

// ------------------------- launch -------------------------
extern "C" void kernel_launch(void* const* d_in, const int* in_sizes, int n_in,
                              void* d_out, int out_size) {
    const float* x      = (const float*)d_in[0];
    const float* wq     = (const float*)d_in[1];
    const float* wk     = (const float*)d_in[2];
    const float* wv     = (const float*)d_in[3];
    const float* w_head = (const float*)d_in[4];
    const float* gamma  = (const float*)d_in[5];
    const float* beta   = (const float*)d_in[6];
    const float* w_proj = (const float*)d_in[7];
    const float* b_proj = (const float*)d_in[8];
    float* out = (float*)d_out;

    k_transpose<<<dim3(8, 8, 3), dim3(32, 32)>>>(wq, wk, wv);
    k_qkv<<<dim3(16, 4, 12), 256>>>(x);
    k_vsum<<<B_ * C_, 256>>>();
    k_score<<<dim3(16, 16, 16), 256>>>();
    k_softmax<<<B_ * T_, 256>>>(w_head);
    k_ssq<<<B_ * NH_, 256>>>();
    k_av<<<dim3(1, 32, 16), 256>>>(gamma, beta);
    k_proj<<<dim3(16, 4, 4), 256>>>(w_proj, b_proj, out);
}

// round 3
// speedup vs baseline: 1.0959x; 1.0959x over previous
#include <cuda_runtime.h>
#include <cstdint>

#define B_  4
#define C_  256
#define NH_ 4
#define D_  64
#define T_  1024
#define EPS_ 1e-5f

// ------------------------- static scratch (no allocs) -------------------------
__device__ float g_wt[3][C_ * C_];          // transposed wq/wk/wv  [c][o]
__device__ float g_q[B_][C_ * T_];
__device__ float g_k[B_][C_ * T_];
__device__ float g_v[B_][C_ * T_];
__device__ float g_s[B_ * NH_][T_ * T_];    // raw per-head scores (scaled)
__device__ float g_a[B_ * NH_][T_ * T_];    // softmax(mixed scores)
__device__ float g_rowsq[B_ * NH_][T_];     // per-row sum(a^2)
__device__ float g_ssq[B_ * NH_];           // total sum(a^2) per (b,g)
__device__ float g_vsum[B_][C_];            // sum over t of v
__device__ float g_x2[B_][T_ * C_];         // reshaped attention output [t'][c']

// ------------------------- mma helpers -------------------------
__device__ __forceinline__ uint32_t f2tf(float f) {
    uint32_t u;
    asm("cvt.rna.tf32.f32 %0, %1;" : "=r"(u) : "f"(f));
    return u;
}

// 3xTF32 split: hi = tf32(f), lo = tf32(f - hi)
__device__ __forceinline__ void f2tf2(float f, uint32_t& hi, uint32_t& lo) {
    hi = f2tf(f);
    lo = f2tf(f - __uint_as_float(hi));
}

__device__ __forceinline__ void mma_tf32(float c[4],
                                         uint32_t a0, uint32_t a1, uint32_t a2, uint32_t a3,
                                         uint32_t b0, uint32_t b1) {
    asm volatile(
        "mma.sync.aligned.m16n8k8.row.col.f32.tf32.tf32.f32 "
        "{%0,%1,%2,%3},{%4,%5,%6,%7},{%8,%9},{%0,%1,%2,%3};\n"
        : "+f"(c[0]), "+f"(c[1]), "+f"(c[2]), "+f"(c[3])
        : "r"(a0), "r"(a1), "r"(a2), "r"(a3), "r"(b0), "r"(b1));
}

// ------------------------- reductions -------------------------
__device__ __forceinline__ float blkReduceSum(float v, float* red) {
    #pragma unroll
    for (int o = 16; o > 0; o >>= 1) v += __shfl_xor_sync(0xffffffffu, v, o);
    if ((threadIdx.x & 31) == 0) red[threadIdx.x >> 5] = v;
    __syncthreads();
    float s = red[0];
    #pragma unroll
    for (int i = 1; i < 8; i++) s += red[i];
    __syncthreads();
    return s;
}

__device__ __forceinline__ float blkReduceMax(float v, float* red) {
    #pragma unroll
    for (int o = 16; o > 0; o >>= 1) v = fmaxf(v, __shfl_xor_sync(0xffffffffu, v, o));
    if ((threadIdx.x & 31) == 0) red[threadIdx.x >> 5] = v;
    __syncthreads();
    float s = red[0];
    #pragma unroll
    for (int i = 1; i < 8; i++) s = fmaxf(s, red[i]);
    __syncthreads();
    return s;
}

// ------------------------- weight transpose -------------------------
__global__ void k_transpose(const float* __restrict__ wq,
                            const float* __restrict__ wk,
                            const float* __restrict__ wv) {
    __shared__ float tile[32][33];
    const float* src = (blockIdx.z == 0) ? wq : ((blockIdx.z == 1) ? wk : wv);
    int c = blockIdx.x * 32 + threadIdx.x;
    int o = blockIdx.y * 32 + threadIdx.y;
    tile[threadIdx.y][threadIdx.x] = src[o * C_ + c];
    __syncthreads();
    int oo = blockIdx.y * 32 + threadIdx.x;
    int cc = blockIdx.x * 32 + threadIdx.y;
    g_wt[blockIdx.z][cc * C_ + oo] = tile[threadIdx.x][threadIdx.y];
}

// ------------------------- fp32 TN GEMM body (for qkv) -------------------------
__device__ __forceinline__ void gemm_tn_body(
    const float* __restrict__ A, int lda,
    const float* __restrict__ B, int ldb,
    float* __restrict__ C, int ldc,
    int K, float alpha, int m0, int n0) {
    __shared__ float As[16][64];
    __shared__ float Bs[16][64];
    float acc[4][4] = {};
    const int tid = threadIdx.x;
    const int lm = tid & 63;
    const int lk = tid >> 6;
    const int ty = tid >> 4;
    const int tx = tid & 15;
    for (int k0 = 0; k0 < K; k0 += 16) {
        #pragma unroll
        for (int p = 0; p < 4; p++) {
            int kk = lk + p * 4;
            As[kk][lm] = A[(k0 + kk) * lda + m0 + lm];
            Bs[kk][lm] = B[(k0 + kk) * ldb + n0 + lm];
        }
        __syncthreads();
        #pragma unroll
        for (int k = 0; k < 16; k++) {
            float4 a4 = *(const float4*)&As[k][ty * 4];
            float4 b4 = *(const float4*)&Bs[k][tx * 4];
            float av[4] = {a4.x, a4.y, a4.z, a4.w};
            float bv[4] = {b4.x, b4.y, b4.z, b4.w};
            #pragma unroll
            for (int i = 0; i < 4; i++)
                #pragma unroll
                for (int j = 0; j < 4; j++)
                    acc[i][j] += av[i] * bv[j];
        }
        __syncthreads();
    }
    #pragma unroll
    for (int i = 0; i < 4; i++) {
        int m = m0 + ty * 4 + i;
        #pragma unroll
        for (int j = 0; j < 4; j++)
            C[m * ldc + n0 + tx * 4 + j] = alpha * acc[i][j];
    }
}

// K1: q/k/v = Wt^T x  -> grid (16, 4, 12)
__global__ void __launch_bounds__(256) k_qkv(const float* __restrict__ x) {
    int z = blockIdx.z;
    int w = z >> 2, b = z & 3;
    float* C = (w == 0) ? g_q[b] : ((w == 1) ? g_k[b] : g_v[b]);
    gemm_tn_body(g_wt[w], C_, x + (size_t)b * C_ * T_, T_, C, T_, C_, 1.0f,
                 blockIdx.y * 64, blockIdx.x * 64);
}

// K2: per-head scores via 3xTF32 mma. s[q,t] = 0.125 * sum_d q[d,q] k[d,t]
// Block tile 128x128, BK=16, 8 warps as 2(m)x4(n), warp tile 64x32.
// grid (8, 8, 16)
__global__ void __launch_bounds__(256) k_score_mma() {
    int z = blockIdx.z;
    int b = z >> 2, h = z & 3;
    const float* A  = g_q[b] + h * D_ * T_;   // [d][q]
    const float* Bk = g_k[b] + h * D_ * T_;   // [d][t]
    float* Cm = g_s[z];
    const int m0 = blockIdx.y * 128;
    const int n0 = blockIdx.x * 128;

    __shared__ uint32_t Ah[16][136], Al[16][136];
    __shared__ uint32_t Bh[16][136], Bl[16][136];

    float acc[4][4][4] = {};           // [mf][nf][reg]
    const int tid = threadIdx.x;
    const int wid = tid >> 5, lane = tid & 31;
    const int wm = wid >> 2, wn = wid & 3;
    const int g = lane >> 2, t = lane & 3;

    for (int k0 = 0; k0 < D_; k0 += 16) {
        const int kk = tid >> 5;             // 0..7
        const int mm = lane * 4;             // 0..124
        float4 a4  = *(const float4*)&A [(k0 + kk)     * T_ + m0 + mm];
        float4 a4h = *(const float4*)&A [(k0 + kk + 8) * T_ + m0 + mm];
        float4 b4  = *(const float4*)&Bk[(k0 + kk)     * T_ + n0 + mm];
        float4 b4h = *(const float4*)&Bk[(k0 + kk + 8) * T_ + n0 + mm];
        f2tf2(a4.x,  Ah[kk][mm],     Al[kk][mm]);
        f2tf2(a4.y,  Ah[kk][mm+1],   Al[kk][mm+1]);
        f2tf2(a4.z,  Ah[kk][mm+2],   Al[kk][mm+2]);
        f2tf2(a4.w,  Ah[kk][mm+3],   Al[kk][mm+3]);
        f2tf2(a4h.x, Ah[kk+8][mm],   Al[kk+8][mm]);
        f2tf2(a4h.y, Ah[kk+8][mm+1], Al[kk+8][mm+1]);
        f2tf2(a4h.z, Ah[kk+8][mm+2], Al[kk+8][mm+2]);
        f2tf2(a4h.w, Ah[kk+8][mm+3], Al[kk+8][mm+3]);
        f2tf2(b4.x,  Bh[kk][mm],     Bl[kk][mm]);
        f2tf2(b4.y,  Bh[kk][mm+1],   Bl[kk][mm+1]);
        f2tf2(b4.z,  Bh[kk][mm+2],   Bl[kk][mm+2]);
        f2tf2(b4.w,  Bh[kk][mm+3],   Bl[kk][mm+3]);
        f2tf2(b4h.x, Bh[kk+8][mm],   Bl[kk+8][mm]);
        f2tf2(b4h.y, Bh[kk+8][mm+1], Bl[kk+8][mm+1]);
        f2tf2(b4h.z, Bh[kk+8][mm+2], Bl[kk+8][mm+2]);
        f2tf2(b4h.w, Bh[kk+8][mm+3], Bl[kk+8][mm+3]);
        __syncthreads();

        #pragma unroll
        for (int ks = 0; ks < 2; ks++) {
            const int kb = ks * 8;
            uint32_t afh[4][4], afl[4][4], bfh[4][2], bfl[4][2];
            #pragma unroll
            for (int mf = 0; mf < 4; mf++) {
                int row = wm * 64 + mf * 16;
                afh[mf][0] = Ah[kb + t    ][row + g];
                afh[mf][1] = Ah[kb + t    ][row + g + 8];
                afh[mf][2] = Ah[kb + t + 4][row + g];
                afh[mf][3] = Ah[kb + t + 4][row + g + 8];
                afl[mf][0] = Al[kb + t    ][row + g];
                afl[mf][1] = Al[kb + t    ][row + g + 8];
                afl[mf][2] = Al[kb + t + 4][row + g];
                afl[mf][3] = Al[kb + t + 4][row + g + 8];
            }
            #pragma unroll
            for (int nf = 0; nf < 4; nf++) {
                int col = wn * 32 + nf * 8;
                bfh[nf][0] = Bh[kb + t    ][col + g];
                bfh[nf][1] = Bh[kb + t + 4][col + g];
                bfl[nf][0] = Bl[kb + t    ][col + g];
                bfl[nf][1] = Bl[kb + t + 4][col + g];
            }
            #pragma unroll
            for (int mf = 0; mf < 4; mf++)
                #pragma unroll
                for (int nf = 0; nf < 4; nf++) {
                    mma_tf32(acc[mf][nf], afh[mf][0], afh[mf][1], afh[mf][2], afh[mf][3],
                             bfl[nf][0], bfl[nf][1]);
                    mma_tf32(acc[mf][nf], afl[mf][0], afl[mf][1], afl[mf][2], afl[mf][3],
                             bfh[nf][0], bfh[nf][1]);
                    mma_tf32(acc[mf][nf], afh[mf][0], afh[mf][1], afh[mf][2], afh[mf][3],
                             bfh[nf][0], bfh[nf][1]);
                }
        }
        __syncthreads();
    }

    const float alpha = 0.125f;
    #pragma unroll
    for (int mf = 0; mf < 4; mf++) {
        int r0 = m0 + wm * 64 + mf * 16 + g;
        #pragma unroll
        for (int nf = 0; nf < 4; nf++) {
            int cc = n0 + wn * 32 + nf * 8 + 2 * t;
            float2 lo = make_float2(alpha * acc[mf][nf][0], alpha * acc[mf][nf][1]);
            float2 hi = make_float2(alpha * acc[mf][nf][2], alpha * acc[mf][nf][3]);
            *(float2*)&Cm[(size_t)r0 * T_ + cc]       = lo;
            *(float2*)&Cm[(size_t)(r0 + 8) * T_ + cc] = hi;
        }
    }
}

// vsum[b][c] = sum_t v[b][c][t]
__global__ void k_vsum() {
    __shared__ float red[8];
    int b = blockIdx.x >> 8, c = blockIdx.x & 255;
    const float* row = g_v[b] + c * T_;
    float s = 0.f;
    for (int i = threadIdx.x; i < T_; i += 256) s += row[i];
    s = blkReduceSum(s, red);
    if (threadIdx.x == 0) g_vsum[b][c] = s;
}

// K3: head-mix + softmax + per-row sum(a^2). grid (B*T), 256 thr
__global__ void __launch_bounds__(256) k_softmax(const float* __restrict__ w_head) {
    __shared__ float rows[NH_][T_];
    __shared__ float red[8];
    int b = blockIdx.x >> 10, qq = blockIdx.x & 1023;
    const int tid = threadIdx.x;

    #pragma unroll
    for (int h = 0; h < NH_; h++)
        for (int i = tid; i < T_; i += 256)
            rows[h][i] = g_s[b * NH_ + h][qq * T_ + i];
    __syncthreads();

    float wh[NH_][NH_];
    #pragma unroll
    for (int g = 0; g < NH_; g++)
        #pragma unroll
        for (int h = 0; h < NH_; h++)
            wh[g][h] = w_head[g * NH_ + h];

    for (int g = 0; g < NH_; g++) {
        float m[4];
        float mx = -3.4e38f;
        #pragma unroll
        for (int j = 0; j < 4; j++) {
            int t = tid + j * 256;
            float v = wh[g][0] * rows[0][t] + wh[g][1] * rows[1][t]
                    + wh[g][2] * rows[2][t] + wh[g][3] * rows[3][t];
            m[j] = v;
            mx = fmaxf(mx, v);
        }
        mx = blkReduceMax(mx, red);
        float e[4], s = 0.f;
        #pragma unroll
        for (int j = 0; j < 4; j++) { e[j] = __expf(m[j] - mx); s += e[j]; }
        s = blkReduceSum(s, red);
        float inv = 1.0f / s;
        float sq = 0.f;
        float* arow = g_a[b * NH_ + g] + qq * T_;
        #pragma unroll
        for (int j = 0; j < 4; j++) {
            float av = e[j] * inv;
            arow[tid + j * 256] = av;
            sq += av * av;
        }
        sq = blkReduceSum(sq, red);
        if (tid == 0) g_rowsq[b * NH_ + g][qq] = sq;
        __syncthreads();
    }
}

// reduce rowsq -> ssq
__global__ void k_ssq() {
    __shared__ float red[8];
    int g = blockIdx.x;
    float s = 0.f;
    for (int i = threadIdx.x; i < T_; i += 256) s += g_rowsq[g][i];
    s = blkReduceSum(s, red);
    if (threadIdx.x == 0) g_ssq[g] = s;
}

// K4: A.V via 3xTF32 mma. out[q,d] = sum_t a[q,t] v[d,t], fold norm, scatter-reshape.
// Block tile 128(m) x 64(n), BK=16, 8 warps as 4(m)x2(n), warp tile 32x32.
// grid (8, 16)
__global__ void __launch_bounds__(256) k_av_mma(const float* __restrict__ gamma,
                                                const float* __restrict__ beta) {
    int z = blockIdx.y;
    int b = z >> 2, h = z & 3;
    const float* A = g_a[z];                 // [q][t]  K contiguous
    const float* V = g_v[b] + h * D_ * T_;   // [d][t]  K contiguous
    const int m0 = blockIdx.x * 128;

    __shared__ uint32_t Ah[128][20], Al[128][20];   // [m][k]
    __shared__ uint32_t Bh[64][20],  Bl[64][20];    // [n][k]

    float acc[2][4][4] = {};           // [mf][nf][reg]
    const int tid = threadIdx.x;
    const int wid = tid >> 5, lane = tid & 31;
    const int wm = wid >> 1, wn = wid & 1;
    const int g = lane >> 2, t = lane & 3;

    for (int k0 = 0; k0 < T_; k0 += 16) {
        {   // load A tile: 128 rows x 16 k; thread: row=tid>>1, half=tid&1 (8 floats)
            int row = tid >> 1, half = tid & 1;
            const float* src = &A[(size_t)(m0 + row) * T_ + k0 + half * 8];
            float4 v0 = *(const float4*)src;
            float4 v1 = *(const float4*)(src + 4);
            int cb = half * 8;
            f2tf2(v0.x, Ah[row][cb],   Al[row][cb]);
            f2tf2(v0.y, Ah[row][cb+1], Al[row][cb+1]);
            f2tf2(v0.z, Ah[row][cb+2], Al[row][cb+2]);
            f2tf2(v0.w, Ah[row][cb+3], Al[row][cb+3]);
            f2tf2(v1.x, Ah[row][cb+4], Al[row][cb+4]);
            f2tf2(v1.y, Ah[row][cb+5], Al[row][cb+5]);
            f2tf2(v1.z, Ah[row][cb+6], Al[row][cb+6]);
            f2tf2(v1.w, Ah[row][cb+7], Al[row][cb+7]);
        }
        {   // load V tile: 64 rows x 16 k; thread: row=tid>>2, q=tid&3 (4 floats)
            int row = tid >> 2, qq = tid & 3;
            float4 v0 = *(const float4*)&V[(size_t)row * T_ + k0 + qq * 4];
            int cb = qq * 4;
            f2tf2(v0.x, Bh[row][cb],   Bl[row][cb]);
            f2tf2(v0.y, Bh[row][cb+1], Bl[row][cb+1]);
            f2tf2(v0.z, Bh[row][cb+2], Bl[row][cb+2]);
            f2tf2(v0.w, Bh[row][cb+3], Bl[row][cb+3]);
        }
        __syncthreads();

        #pragma unroll
        for (int ks = 0; ks < 2; ks++) {
            const int kb = ks * 8;
            uint32_t afh[2][4], afl[2][4], bfh[4][2], bfl[4][2];
            #pragma unroll
            for (int mf = 0; mf < 2; mf++) {
                int row = wm * 32 + mf * 16;
                afh[mf][0] = Ah[row + g    ][kb + t];
                afh[mf][1] = Ah[row + g + 8][kb + t];
                afh[mf][2] = Ah[row + g    ][kb + t + 4];
                afh[mf][3] = Ah[row + g + 8][kb + t + 4];
                afl[mf][0] = Al[row + g    ][kb + t];
                afl[mf][1] = Al[row + g + 8][kb + t];
                afl[mf][2] = Al[row + g    ][kb + t + 4];
                afl[mf][3] = Al[row + g + 8][kb + t + 4];
            }
            #pragma unroll
            for (int nf = 0; nf < 4; nf++) {
                int col = wn * 32 + nf * 8;
                bfh[nf][0] = Bh[col + g][kb + t];
                bfh[nf][1] = Bh[col + g][kb + t + 4];
                bfl[nf][0] = Bl[col + g][kb + t];
                bfl[nf][1] = Bl[col + g][kb + t + 4];
            }
            #pragma unroll
            for (int mf = 0; mf < 2; mf++)
                #pragma unroll
                for (int nf = 0; nf < 4; nf++) {
                    mma_tf32(acc[mf][nf], afh[mf][0], afh[mf][1], afh[mf][2], afh[mf][3],
                             bfl[nf][0], bfl[nf][1]);
                    mma_tf32(acc[mf][nf], afl[mf][0], afl[mf][1], afl[mf][2], afl[mf][3],
                             bfh[nf][0], bfh[nf][1]);
                    mma_tf32(acc[mf][nf], afh[mf][0], afh[mf][1], afh[mf][2], afh[mf][3],
                             bfh[nf][0], bfh[nf][1]);
                }
        }
        __syncthreads();
    }

    // fold InstanceNorm: mean = 1/T exactly; var = ssq/T^2 - mu^2
    const float mu  = 1.0f / (float)T_;
    const float var = g_ssq[z] * (1.0f / ((float)T_ * (float)T_)) - mu * mu;
    const float invs = rsqrtf(var + EPS_);
    const float c1 = gamma[h] * invs;
    const float c0 = beta[h] - c1 * mu;

    #pragma unroll
    for (int mf = 0; mf < 2; mf++) {
        #pragma unroll
        for (int rr = 0; rr < 2; rr++) {
            int q = m0 + wm * 32 + mf * 16 + g + rr * 8;
            int xrow  = h * 256 + (q >> 2);
            int cbase = (q & 3) * 64;
            #pragma unroll
            for (int nf = 0; nf < 4; nf++) {
                int d = wn * 32 + nf * 8 + 2 * t;
                float vs0 = g_vsum[b][h * D_ + d];
                float vs1 = g_vsum[b][h * D_ + d + 1];
                float o0 = c1 * acc[mf][nf][rr * 2]     + c0 * vs0;
                float o1 = c1 * acc[mf][nf][rr * 2 + 1] + c0 * vs1;
                *(float2*)&g_x2[b][(size_t)xrow * C_ + cbase + d] = make_float2(o0, o1);
            }
        }
    }
}

// K5: NT GEMM  y[o,t'] = sum_c wp[o,c] * X[t',c] + bias[o]
__global__ void __launch_bounds__(256) k_proj(const float* __restrict__ wp,
                                              const float* __restrict__ bp,
                                              float* __restrict__ out) {
    int b = blockIdx.z;
    int m0 = blockIdx.y * 64;
    int n0 = blockIdx.x * 64;
    __shared__ float Ast[16][68];
    __shared__ float Bst[16][68];
    float acc[4][4] = {};
    const int tid = threadIdx.x;
    const int lk = tid & 15, lr = tid >> 4;
    const int ty = tid >> 4, tx = tid & 15;
    const float* X = g_x2[b];
    for (int k0 = 0; k0 < C_; k0 += 16) {
        #pragma unroll
        for (int p = 0; p < 4; p++) {
            Ast[lk][lr + p * 16] = wp[(m0 + lr + p * 16) * C_ + k0 + lk];
            Bst[lk][lr + p * 16] = X[(n0 + lr + p * 16) * C_ + k0 + lk];
        }
        __syncthreads();
        #pragma unroll
        for (int k = 0; k < 16; k++) {
            float4 a4 = *(const float4*)&Ast[k][ty * 4];
            float4 b4 = *(const float4*)&Bst[k][tx * 4];
            float av[4] = {a4.x, a4.y, a4.z, a4.w};
            float bv[4] = {b4.x, b4.y, b4.z, b4.w};
            #pragma unroll
            for (int i = 0; i < 4; i++)
                #pragma unroll
                for (int j = 0; j < 4; j++)
                    acc[i][j] += av[i] * bv[j];
        }
        __syncthreads();
    }
    #pragma unroll
    for (int i = 0; i < 4; i++) {
        int o = m0 + ty * 4 + i;
        float bias = bp[o];
        #pragma unroll
        for (int j = 0; j < 4; j++)
            out[(size_t)b * C_ * T_ + o * T_ + n0 + tx * 4 + j] = acc[i][j] + bias;
    }
}

// ------------------------- launch -------------------------
extern "C" void kernel_launch(void* const* d_in, const int* in_sizes, int n_in,
                              void* d_out, int out_size) {
    const float* x      = (const float*)d_in[0];
    const float* wq     = (const float*)d_in[1];
    const float* wk     = (const float*)d_in[2];
    const float* wv     = (const float*)d_in[3];
    const float* w_head = (const float*)d_in[4];
    const float* gamma  = (const float*)d_in[5];
    const float* beta   = (const float*)d_in[6];
    const float* w_proj = (const float*)d_in[7];
    const float* b_proj = (const float*)d_in[8];
    float* out = (float*)d_out;

    k_transpose<<<dim3(8, 8, 3), dim3(32, 32)>>>(wq, wk, wv);
    k_qkv<<<dim3(16, 4, 12), 256>>>(x);
    k_vsum<<<B_ * C_, 256>>>();
    k_score_mma<<<dim3(8, 8, 16), 256>>>();
    k_softmax<<<B_ * T_, 256>>>(w_head);
    k_ssq<<<B_ * NH_, 256>>>();
    k_av_mma<<<dim3(8, 16), 256>>>(gamma, beta);
    k_proj<<<dim3(16, 4, 4), 256>>>(w_proj, b_proj, out);
}

// round 4
// speedup vs baseline: 1.1322x; 1.0331x over previous
#include <cuda_runtime.h>
#include <cstdint>

#define B_  4
#define C_  256
#define NH_ 4
#define D_  64
#define T_  1024
#define EPS_ 1e-5f

// ------------------------- static scratch (no allocs) -------------------------
__device__ float g_wt[3][C_ * C_];            // transposed wq/wk/wv  [c][o]
__device__ float g_v[B_][C_ * T_];            // fp32 V (for vsum)
__device__ uint32_t g_qh[B_][C_ * T_];        // tf32 hi/lo planes
__device__ uint32_t g_ql[B_][C_ * T_];
__device__ uint32_t g_kh[B_][C_ * T_];
__device__ uint32_t g_kl[B_][C_ * T_];
__device__ uint32_t g_vh[B_][C_ * T_];
__device__ uint32_t g_vl[B_][C_ * T_];
__device__ float g_s[B_ * NH_][T_ * T_];      // raw per-head scores (scaled)
__device__ float g_a[B_ * NH_][T_ * T_];      // softmax(mixed scores)
__device__ float g_rowsq[B_ * NH_][T_];       // per-row sum(a^2)
__device__ float g_ssq[B_ * NH_];             // total sum(a^2) per (b,g)
__device__ float g_vsum[B_][C_];              // sum over t of v
__device__ float g_x2[B_][T_ * C_];           // reshaped attention output [t'][c']

// ------------------------- mma helpers -------------------------
__device__ __forceinline__ uint32_t f2tf(float f) {
    uint32_t u;
    asm("cvt.rna.tf32.f32 %0, %1;" : "=r"(u) : "f"(f));
    return u;
}

// 3xTF32 split: hi = tf32(f), lo = tf32(f - hi)
__device__ __forceinline__ void f2tf2(float f, uint32_t& hi, uint32_t& lo) {
    hi = f2tf(f);
    lo = f2tf(f - __uint_as_float(hi));
}

__device__ __forceinline__ void mma_tf32(float c[4],
                                         uint32_t a0, uint32_t a1, uint32_t a2, uint32_t a3,
                                         uint32_t b0, uint32_t b1) {
    asm volatile(
        "mma.sync.aligned.m16n8k8.row.col.f32.tf32.tf32.f32 "
        "{%0,%1,%2,%3},{%4,%5,%6,%7},{%8,%9},{%0,%1,%2,%3};\n"
        : "+f"(c[0]), "+f"(c[1]), "+f"(c[2]), "+f"(c[3])
        : "r"(a0), "r"(a1), "r"(a2), "r"(a3), "r"(b0), "r"(b1));
}

// ------------------------- reductions -------------------------
__device__ __forceinline__ float blkReduceSum(float v, float* red) {
    #pragma unroll
    for (int o = 16; o > 0; o >>= 1) v += __shfl_xor_sync(0xffffffffu, v, o);
    if ((threadIdx.x & 31) == 0) red[threadIdx.x >> 5] = v;
    __syncthreads();
    float s = red[0];
    #pragma unroll
    for (int i = 1; i < 8; i++) s += red[i];
    __syncthreads();
    return s;
}

__device__ __forceinline__ float blkReduceMax(float v, float* red) {
    #pragma unroll
    for (int o = 16; o > 0; o >>= 1) v = fmaxf(v, __shfl_xor_sync(0xffffffffu, v, o));
    if ((threadIdx.x & 31) == 0) red[threadIdx.x >> 5] = v;
    __syncthreads();
    float s = red[0];
    #pragma unroll
    for (int i = 1; i < 8; i++) s = fmaxf(s, red[i]);
    __syncthreads();
    return s;
}

// ------------------------- weight transpose -------------------------
__global__ void k_transpose(const float* __restrict__ wq,
                            const float* __restrict__ wk,
                            const float* __restrict__ wv) {
    __shared__ float tile[32][33];
    const float* src = (blockIdx.z == 0) ? wq : ((blockIdx.z == 1) ? wk : wv);
    int c = blockIdx.x * 32 + threadIdx.x;
    int o = blockIdx.y * 32 + threadIdx.y;
    tile[threadIdx.y][threadIdx.x] = src[o * C_ + c];
    __syncthreads();
    int oo = blockIdx.y * 32 + threadIdx.x;
    int cc = blockIdx.x * 32 + threadIdx.y;
    g_wt[blockIdx.z][cc * C_ + oo] = tile[threadIdx.x][threadIdx.y];
}

// K1: q/k/v = Wt^T x ; epilogue writes tf32 hi/lo planes.  grid (16, 4, 12)
__global__ void __launch_bounds__(256) k_qkv(const float* __restrict__ x) {
    int z = blockIdx.z;
    int w = z >> 2, b = z & 3;
    const float* A = g_wt[w];
    const float* Bx = x + (size_t)b * C_ * T_;
    const int m0 = blockIdx.y * 64, n0 = blockIdx.x * 64;

    __shared__ float As[16][64];
    __shared__ float Bs[16][64];
    float acc[4][4] = {};
    const int tid = threadIdx.x;
    const int lm = tid & 63;
    const int lk = tid >> 6;
    const int ty = tid >> 4;
    const int tx = tid & 15;
    for (int k0 = 0; k0 < C_; k0 += 16) {
        #pragma unroll
        for (int p = 0; p < 4; p++) {
            int kk = lk + p * 4;
            As[kk][lm] = A[(k0 + kk) * C_ + m0 + lm];
            Bs[kk][lm] = Bx[(k0 + kk) * T_ + n0 + lm];
        }
        __syncthreads();
        #pragma unroll
        for (int k = 0; k < 16; k++) {
            float4 a4 = *(const float4*)&As[k][ty * 4];
            float4 b4 = *(const float4*)&Bs[k][tx * 4];
            float av[4] = {a4.x, a4.y, a4.z, a4.w};
            float bv[4] = {b4.x, b4.y, b4.z, b4.w};
            #pragma unroll
            for (int i = 0; i < 4; i++)
                #pragma unroll
                for (int j = 0; j < 4; j++)
                    acc[i][j] += av[i] * bv[j];
        }
        __syncthreads();
    }
    uint32_t* ph = (w == 0) ? g_qh[b] : ((w == 1) ? g_kh[b] : g_vh[b]);
    uint32_t* pl = (w == 0) ? g_ql[b] : ((w == 1) ? g_kl[b] : g_vl[b]);
    #pragma unroll
    for (int i = 0; i < 4; i++) {
        int m = m0 + ty * 4 + i;
        #pragma unroll
        for (int j = 0; j < 4; j++) {
            int n = n0 + tx * 4 + j;
            float val = acc[i][j];
            uint32_t hi, lo;
            f2tf2(val, hi, lo);
            ph[(size_t)m * T_ + n] = hi;
            pl[(size_t)m * T_ + n] = lo;
            if (w == 2) g_v[b][(size_t)m * T_ + n] = val;
        }
    }
}

// K2: per-head scores via 3xTF32 mma from precomputed planes.
// Block tile 128x128, BK=16, 8 warps as 2(m)x4(n), warp tile 64x32.  grid (8, 8, 16)
__global__ void __launch_bounds__(256) k_score_mma() {
    int z = blockIdx.z;
    int b = z >> 2, h = z & 3;
    const uint32_t* Aph = g_qh[b] + h * D_ * T_;   // [d][q]
    const uint32_t* Apl = g_ql[b] + h * D_ * T_;
    const uint32_t* Bph = g_kh[b] + h * D_ * T_;   // [d][t]
    const uint32_t* Bpl = g_kl[b] + h * D_ * T_;
    float* Cm = g_s[z];
    const int m0 = blockIdx.y * 128;
    const int n0 = blockIdx.x * 128;

    __shared__ uint32_t Ah[16][136], Al[16][136];
    __shared__ uint32_t Bh[16][136], Bl[16][136];

    float acc[4][4][4] = {};           // [mf][nf][reg]
    const int tid = threadIdx.x;
    const int wid = tid >> 5, lane = tid & 31;
    const int wm = wid >> 2, wn = wid & 3;
    const int g = lane >> 2, t = lane & 3;

    for (int k0 = 0; k0 < D_; k0 += 16) {
        const int kk = tid >> 5;             // 0..7
        const int mm = lane * 4;             // 0..124
        const size_t r0 = (size_t)(k0 + kk) * T_;
        const size_t r8 = (size_t)(k0 + kk + 8) * T_;
        *(uint4*)&Ah[kk][mm]     = *(const uint4*)&Aph[r0 + m0 + mm];
        *(uint4*)&Ah[kk + 8][mm] = *(const uint4*)&Aph[r8 + m0 + mm];
        *(uint4*)&Al[kk][mm]     = *(const uint4*)&Apl[r0 + m0 + mm];
        *(uint4*)&Al[kk + 8][mm] = *(const uint4*)&Apl[r8 + m0 + mm];
        *(uint4*)&Bh[kk][mm]     = *(const uint4*)&Bph[r0 + n0 + mm];
        *(uint4*)&Bh[kk + 8][mm] = *(const uint4*)&Bph[r8 + n0 + mm];
        *(uint4*)&Bl[kk][mm]     = *(const uint4*)&Bpl[r0 + n0 + mm];
        *(uint4*)&Bl[kk + 8][mm] = *(const uint4*)&Bpl[r8 + n0 + mm];
        __syncthreads();

        #pragma unroll
        for (int ks = 0; ks < 2; ks++) {
            const int kb = ks * 8;
            uint32_t afh[4][4], afl[4][4], bfh[4][2], bfl[4][2];
            #pragma unroll
            for (int mf = 0; mf < 4; mf++) {
                int row = wm * 64 + mf * 16;
                afh[mf][0] = Ah[kb + t    ][row + g];
                afh[mf][1] = Ah[kb + t    ][row + g + 8];
                afh[mf][2] = Ah[kb + t + 4][row + g];
                afh[mf][3] = Ah[kb + t + 4][row + g + 8];
                afl[mf][0] = Al[kb + t    ][row + g];
                afl[mf][1] = Al[kb + t    ][row + g + 8];
                afl[mf][2] = Al[kb + t + 4][row + g];
                afl[mf][3] = Al[kb + t + 4][row + g + 8];
            }
            #pragma unroll
            for (int nf = 0; nf < 4; nf++) {
                int col = wn * 32 + nf * 8;
                bfh[nf][0] = Bh[kb + t    ][col + g];
                bfh[nf][1] = Bh[kb + t + 4][col + g];
                bfl[nf][0] = Bl[kb + t    ][col + g];
                bfl[nf][1] = Bl[kb + t + 4][col + g];
            }
            #pragma unroll
            for (int mf = 0; mf < 4; mf++)
                #pragma unroll
                for (int nf = 0; nf < 4; nf++) {
                    mma_tf32(acc[mf][nf], afh[mf][0], afh[mf][1], afh[mf][2], afh[mf][3],
                             bfl[nf][0], bfl[nf][1]);
                    mma_tf32(acc[mf][nf], afl[mf][0], afl[mf][1], afl[mf][2], afl[mf][3],
                             bfh[nf][0], bfh[nf][1]);
                    mma_tf32(acc[mf][nf], afh[mf][0], afh[mf][1], afh[mf][2], afh[mf][3],
                             bfh[nf][0], bfh[nf][1]);
                }
        }
        __syncthreads();
    }

    const float alpha = 0.125f;
    #pragma unroll
    for (int mf = 0; mf < 4; mf++) {
        int r0 = m0 + wm * 64 + mf * 16 + g;
        #pragma unroll
        for (int nf = 0; nf < 4; nf++) {
            int cc = n0 + wn * 32 + nf * 8 + 2 * t;
            float2 lo = make_float2(alpha * acc[mf][nf][0], alpha * acc[mf][nf][1]);
            float2 hi = make_float2(alpha * acc[mf][nf][2], alpha * acc[mf][nf][3]);
            *(float2*)&Cm[(size_t)r0 * T_ + cc]       = lo;
            *(float2*)&Cm[(size_t)(r0 + 8) * T_ + cc] = hi;
        }
    }
}

// vsum[b][c] = sum_t v[b][c][t]
__global__ void k_vsum() {
    __shared__ float red[8];
    int b = blockIdx.x >> 8, c = blockIdx.x & 255;
    const float* row = g_v[b] + c * T_;
    float s = 0.f;
    for (int i = threadIdx.x; i < T_; i += 256) s += row[i];
    s = blkReduceSum(s, red);
    if (threadIdx.x == 0) g_vsum[b][c] = s;
}

// K3: head-mix + softmax + per-row sum(a^2). grid (B*T), 256 thr
__global__ void __launch_bounds__(256) k_softmax(const float* __restrict__ w_head) {
    __shared__ float rows[NH_][T_];
    __shared__ float red[8];
    int b = blockIdx.x >> 10, qq = blockIdx.x & 1023;
    const int tid = threadIdx.x;

    #pragma unroll
    for (int h = 0; h < NH_; h++)
        for (int i = tid; i < T_; i += 256)
            rows[h][i] = g_s[b * NH_ + h][qq * T_ + i];
    __syncthreads();

    float wh[NH_][NH_];
    #pragma unroll
    for (int g = 0; g < NH_; g++)
        #pragma unroll
        for (int h = 0; h < NH_; h++)
            wh[g][h] = w_head[g * NH_ + h];

    for (int g = 0; g < NH_; g++) {
        float m[4];
        float mx = -3.4e38f;
        #pragma unroll
        for (int j = 0; j < 4; j++) {
            int t = tid + j * 256;
            float v = wh[g][0] * rows[0][t] + wh[g][1] * rows[1][t]
                    + wh[g][2] * rows[2][t] + wh[g][3] * rows[3][t];
            m[j] = v;
            mx = fmaxf(mx, v);
        }
        mx = blkReduceMax(mx, red);
        float e[4], s = 0.f;
        #pragma unroll
        for (int j = 0; j < 4; j++) { e[j] = __expf(m[j] - mx); s += e[j]; }
        s = blkReduceSum(s, red);
        float inv = 1.0f / s;
        float sq = 0.f;
        float* arow = g_a[b * NH_ + g] + qq * T_;
        #pragma unroll
        for (int j = 0; j < 4; j++) {
            float av = e[j] * inv;
            arow[tid + j * 256] = av;
            sq += av * av;
        }
        sq = blkReduceSum(sq, red);
        if (tid == 0) g_rowsq[b * NH_ + g][qq] = sq;
        __syncthreads();
    }
}

// reduce rowsq -> ssq
__global__ void k_ssq() {
    __shared__ float red[8];
    int g = blockIdx.x;
    float s = 0.f;
    for (int i = threadIdx.x; i < T_; i += 256) s += g_rowsq[g][i];
    s = blkReduceSum(s, red);
    if (threadIdx.x == 0) g_ssq[g] = s;
}

// K4: A.V via 3xTF32 mma. out[q,d] = sum_t a[q,t] v[d,t], fold norm, scatter-reshape.
// Block tile 128(m) x 64(n), BK=16, 8 warps as 4(m)x2(n), warp tile 32x32.  grid (8, 16)
__global__ void __launch_bounds__(256) k_av_mma(const float* __restrict__ gamma,
                                                const float* __restrict__ beta) {
    int z = blockIdx.y;
    int b = z >> 2, h = z & 3;
    const float* A = g_a[z];                        // [q][t]  K contiguous
    const uint32_t* Vph = g_vh[b] + h * D_ * T_;    // [d][t]
    const uint32_t* Vpl = g_vl[b] + h * D_ * T_;
    const int m0 = blockIdx.x * 128;

    __shared__ uint32_t Ah[128][20], Al[128][20];   // [m][k]
    __shared__ uint32_t Bh[64][20],  Bl[64][20];    // [n][k]

    float acc[2][4][4] = {};           // [mf][nf][reg]
    const int tid = threadIdx.x;
    const int wid = tid >> 5, lane = tid & 31;
    const int wm = wid >> 1, wn = wid & 1;
    const int g = lane >> 2, t = lane & 3;

    for (int k0 = 0; k0 < T_; k0 += 16) {
        {   // load A tile: 128 rows x 16 k; thread: row=tid>>1, half=tid&1 (8 floats)
            int row = tid >> 1, half = tid & 1;
            const float* src = &A[(size_t)(m0 + row) * T_ + k0 + half * 8];
            float4 v0 = *(const float4*)src;
            float4 v1 = *(const float4*)(src + 4);
            uint32_t h4[8], l4[8];
            f2tf2(v0.x, h4[0], l4[0]);  f2tf2(v0.y, h4[1], l4[1]);
            f2tf2(v0.z, h4[2], l4[2]);  f2tf2(v0.w, h4[3], l4[3]);
            f2tf2(v1.x, h4[4], l4[4]);  f2tf2(v1.y, h4[5], l4[5]);
            f2tf2(v1.z, h4[6], l4[6]);  f2tf2(v1.w, h4[7], l4[7]);
            int cb = half * 8;
            *(uint4*)&Ah[row][cb]     = *(uint4*)&h4[0];
            *(uint4*)&Ah[row][cb + 4] = *(uint4*)&h4[4];
            *(uint4*)&Al[row][cb]     = *(uint4*)&l4[0];
            *(uint4*)&Al[row][cb + 4] = *(uint4*)&l4[4];
        }
        {   // load V tile from planes: 64 rows x 16 k; thread: row=tid>>2, q=tid&3
            int row = tid >> 2, qq = tid & 3;
            const size_t off = (size_t)row * T_ + k0 + qq * 4;
            *(uint4*)&Bh[row][qq * 4] = *(const uint4*)&Vph[off];
            *(uint4*)&Bl[row][qq * 4] = *(const uint4*)&Vpl[off];
        }
        __syncthreads();

        #pragma unroll
        for (int ks = 0; ks < 2; ks++) {
            const int kb = ks * 8;
            uint32_t afh[2][4], afl[2][4], bfh[4][2], bfl[4][2];
            #pragma unroll
            for (int mf = 0; mf < 2; mf++) {
                int row = wm * 32 + mf * 16;
                afh[mf][0] = Ah[row + g    ][kb + t];
                afh[mf][1] = Ah[row + g + 8][kb + t];
                afh[mf][2] = Ah[row + g    ][kb + t + 4];
                afh[mf][3] = Ah[row + g + 8][kb + t + 4];
                afl[mf][0] = Al[row + g    ][kb + t];
                afl[mf][1] = Al[row + g + 8][kb + t];
                afl[mf][2] = Al[row + g    ][kb + t + 4];
                afl[mf][3] = Al[row + g + 8][kb + t + 4];
            }
            #pragma unroll
            for (int nf = 0; nf < 4; nf++) {
                int col = wn * 32 + nf * 8;
                bfh[nf][0] = Bh[col + g][kb + t];
                bfh[nf][1] = Bh[col + g][kb + t + 4];
                bfl[nf][0] = Bl[col + g][kb + t];
                bfl[nf][1] = Bl[col + g][kb + t + 4];
            }
            #pragma unroll
            for (int mf = 0; mf < 2; mf++)
                #pragma unroll
                for (int nf = 0; nf < 4; nf++) {
                    mma_tf32(acc[mf][nf], afh[mf][0], afh[mf][1], afh[mf][2], afh[mf][3],
                             bfl[nf][0], bfl[nf][1]);
                    mma_tf32(acc[mf][nf], afl[mf][0], afl[mf][1], afl[mf][2], afl[mf][3],
                             bfh[nf][0], bfh[nf][1]);
                    mma_tf32(acc[mf][nf], afh[mf][0], afh[mf][1], afh[mf][2], afh[mf][3],
                             bfh[nf][0], bfh[nf][1]);
                }
        }
        __syncthreads();
    }

    // fold InstanceNorm: mean = 1/T exactly; var = ssq/T^2 - mu^2
    const float mu  = 1.0f / (float)T_;
    const float var = g_ssq[z] * (1.0f / ((float)T_ * (float)T_)) - mu * mu;
    const float invs = rsqrtf(var + EPS_);
    const float c1 = gamma[h] * invs;
    const float c0 = beta[h] - c1 * mu;

    #pragma unroll
    for (int mf = 0; mf < 2; mf++) {
        #pragma unroll
        for (int rr = 0; rr < 2; rr++) {
            int q = m0 + wm * 32 + mf * 16 + g + rr * 8;
            int xrow  = h * 256 + (q >> 2);
            int cbase = (q & 3) * 64;
            #pragma unroll
            for (int nf = 0; nf < 4; nf++) {
                int d = wn * 32 + nf * 8 + 2 * t;
                float vs0 = g_vsum[b][h * D_ + d];
                float vs1 = g_vsum[b][h * D_ + d + 1];
                float o0 = c1 * acc[mf][nf][rr * 2]     + c0 * vs0;
                float o1 = c1 * acc[mf][nf][rr * 2 + 1] + c0 * vs1;
                *(float2*)&g_x2[b][(size_t)xrow * C_ + cbase + d] = make_float2(o0, o1);
            }
        }
    }
}

// K5: NT GEMM  y[o,t'] = sum_c wp[o,c] * X[t',c] + bias[o]
__global__ void __launch_bounds__(256) k_proj(const float* __restrict__ wp,
                                              const float* __restrict__ bp,
                                              float* __restrict__ out) {
    int b = blockIdx.z;
    int m0 = blockIdx.y * 64;
    int n0 = blockIdx.x * 64;
    __shared__ float Ast[16][68];
    __shared__ float Bst[16][68];
    float acc[4][4] = {};
    const int tid = threadIdx.x;
    const int lk = tid & 15, lr = tid >> 4;
    const int ty = tid >> 4, tx = tid & 15;
    const float* X = g_x2[b];
    for (int k0 = 0; k0 < C_; k0 += 16) {
        #pragma unroll
        for (int p = 0; p < 4; p++) {
            Ast[lk][lr + p * 16] = wp[(m0 + lr + p * 16) * C_ + k0 + lk];
            Bst[lk][lr + p * 16] = X[(n0 + lr + p * 16) * C_ + k0 + lk];
        }
        __syncthreads();
        #pragma unroll
        for (int k = 0; k < 16; k++) {
            float4 a4 = *(const float4*)&Ast[k][ty * 4];
            float4 b4 = *(const float4*)&Bst[k][tx * 4];
            float av[4] = {a4.x, a4.y, a4.z, a4.w};
            float bv[4] = {b4.x, b4.y, b4.z, b4.w};
            #pragma unroll
            for (int i = 0; i < 4; i++)
                #pragma unroll
                for (int j = 0; j < 4; j++)
                    acc[i][j] += av[i] * bv[j];
        }
        __syncthreads();
    }
    #pragma unroll
    for (int i = 0; i < 4; i++) {
        int o = m0 + ty * 4 + i;
        float bias = bp[o];
        #pragma unroll
        for (int j = 0; j < 4; j++)
            out[(size_t)b * C_ * T_ + o * T_ + n0 + tx * 4 + j] = acc[i][j] + bias;
    }
}

// ------------------------- launch -------------------------
extern "C" void kernel_launch(void* const* d_in, const int* in_sizes, int n_in,
                              void* d_out, int out_size) {
    const float* x      = (const float*)d_in[0];
    const float* wq     = (const float*)d_in[1];
    const float* wk     = (const float*)d_in[2];
    const float* wv     = (const float*)d_in[3];
    const float* w_head = (const float*)d_in[4];
    const float* gamma  = (const float*)d_in[5];
    const float* beta   = (const float*)d_in[6];
    const float* w_proj = (const float*)d_in[7];
    const float* b_proj = (const float*)d_in[8];
    float* out = (float*)d_out;

    k_transpose<<<dim3(8, 8, 3), dim3(32, 32)>>>(wq, wk, wv);
    k_qkv<<<dim3(16, 4, 12), 256>>>(x);
    k_vsum<<<B_ * C_, 256>>>();
    k_score_mma<<<dim3(8, 8, 16), 256>>>();
    k_softmax<<<B_ * T_, 256>>>(w_head);
    k_ssq<<<B_ * NH_, 256>>>();
    k_av_mma<<<dim3(8, 16), 256>>>(gamma, beta);
    k_proj<<<dim3(16, 4, 4), 256>>>(w_proj, b_proj, out);
}

// round 5
// speedup vs baseline: 1.3765x; 1.2157x over previous
#include <cuda_runtime.h>
#include <cstdint>

#define B_  4
#define C_  256
#define NH_ 4
#define D_  64
#define T_  1024
#define EPS_ 1e-5f

// ------------------------- static scratch (no allocs) -------------------------
__device__ float g_wt[3][C_ * C_];            // transposed wq/wk/wv  [c][o]
__device__ float g_v[B_][C_ * T_];            // fp32 V (for vsum)
__device__ uint32_t g_qh[B_][C_ * T_];        // tf32 hi/lo planes
__device__ uint32_t g_ql[B_][C_ * T_];
__device__ uint32_t g_kh[B_][C_ * T_];
__device__ uint32_t g_kl[B_][C_ * T_];
__device__ uint32_t g_vh[B_][C_ * T_];
__device__ uint32_t g_vl[B_][C_ * T_];
__device__ float g_s[B_ * NH_][T_ * T_];      // raw per-head scores (scaled)
__device__ float g_a[B_ * NH_][T_ * T_];      // softmax(mixed scores)
__device__ float g_rowsq[B_ * NH_][T_];       // per-row sum(a^2)
__device__ float g_ssq[B_ * NH_];             // total sum(a^2) per (b,g)
__device__ float g_vsum[B_][C_];              // sum over t of v
__device__ float g_x2[B_][T_ * C_];           // reshaped attention output [t'][c']

// ------------------------- mma / async helpers -------------------------
__device__ __forceinline__ uint32_t f2tf(float f) {
    uint32_t u;
    asm("cvt.rna.tf32.f32 %0, %1;" : "=r"(u) : "f"(f));
    return u;
}

__device__ __forceinline__ void f2tf2(float f, uint32_t& hi, uint32_t& lo) {
    hi = f2tf(f);
    lo = f2tf(f - __uint_as_float(hi));
}

__device__ __forceinline__ void mma_tf32(float c[4],
                                         uint32_t a0, uint32_t a1, uint32_t a2, uint32_t a3,
                                         uint32_t b0, uint32_t b1) {
    asm volatile(
        "mma.sync.aligned.m16n8k8.row.col.f32.tf32.tf32.f32 "
        "{%0,%1,%2,%3},{%4,%5,%6,%7},{%8,%9},{%0,%1,%2,%3};\n"
        : "+f"(c[0]), "+f"(c[1]), "+f"(c[2]), "+f"(c[3])
        : "r"(a0), "r"(a1), "r"(a2), "r"(a3), "r"(b0), "r"(b1));
}

__device__ __forceinline__ void cpasync16(uint32_t* smem_dst, const uint32_t* gmem_src) {
    uint32_t s = (uint32_t)__cvta_generic_to_shared(smem_dst);
    asm volatile("cp.async.cg.shared.global [%0], [%1], 16;\n" :: "r"(s), "l"(gmem_src));
}
#define CP_COMMIT() asm volatile("cp.async.commit_group;\n")
#define CP_WAIT0()  asm volatile("cp.async.wait_group 0;\n")

// ------------------------- reductions -------------------------
__device__ __forceinline__ float blkReduceSum(float v, float* red) {
    #pragma unroll
    for (int o = 16; o > 0; o >>= 1) v += __shfl_xor_sync(0xffffffffu, v, o);
    if ((threadIdx.x & 31) == 0) red[threadIdx.x >> 5] = v;
    __syncthreads();
    float s = red[0];
    #pragma unroll
    for (int i = 1; i < 8; i++) s += red[i];
    __syncthreads();
    return s;
}

__device__ __forceinline__ float blkReduceMax(float v, float* red) {
    #pragma unroll
    for (int o = 16; o > 0; o >>= 1) v = fmaxf(v, __shfl_xor_sync(0xffffffffu, v, o));
    if ((threadIdx.x & 31) == 0) red[threadIdx.x >> 5] = v;
    __syncthreads();
    float s = red[0];
    #pragma unroll
    for (int i = 1; i < 8; i++) s = fmaxf(s, red[i]);
    __syncthreads();
    return s;
}

// ------------------------- weight transpose -------------------------
__global__ void k_transpose(const float* __restrict__ wq,
                            const float* __restrict__ wk,
                            const float* __restrict__ wv) {
    __shared__ float tile[32][33];
    const float* src = (blockIdx.z == 0) ? wq : ((blockIdx.z == 1) ? wk : wv);
    int c = blockIdx.x * 32 + threadIdx.x;
    int o = blockIdx.y * 32 + threadIdx.y;
    tile[threadIdx.y][threadIdx.x] = src[o * C_ + c];
    __syncthreads();
    int oo = blockIdx.y * 32 + threadIdx.x;
    int cc = blockIdx.x * 32 + threadIdx.y;
    g_wt[blockIdx.z][cc * C_ + oo] = tile[threadIdx.x][threadIdx.y];
}

// K1: q/k/v = Wt^T x ; epilogue writes tf32 hi/lo planes.  grid (16, 4, 12)
__global__ void __launch_bounds__(256) k_qkv(const float* __restrict__ x) {
    int z = blockIdx.z;
    int w = z >> 2, b = z & 3;
    const float* A = g_wt[w];
    const float* Bx = x + (size_t)b * C_ * T_;
    const int m0 = blockIdx.y * 64, n0 = blockIdx.x * 64;

    __shared__ float As[16][64];
    __shared__ float Bs[16][64];
    float acc[4][4] = {};
    const int tid = threadIdx.x;
    const int lm = tid & 63;
    const int lk = tid >> 6;
    const int ty = tid >> 4;
    const int tx = tid & 15;
    for (int k0 = 0; k0 < C_; k0 += 16) {
        #pragma unroll
        for (int p = 0; p < 4; p++) {
            int kk = lk + p * 4;
            As[kk][lm] = A[(k0 + kk) * C_ + m0 + lm];
            Bs[kk][lm] = Bx[(k0 + kk) * T_ + n0 + lm];
        }
        __syncthreads();
        #pragma unroll
        for (int k = 0; k < 16; k++) {
            float4 a4 = *(const float4*)&As[k][ty * 4];
            float4 b4 = *(const float4*)&Bs[k][tx * 4];
            float av[4] = {a4.x, a4.y, a4.z, a4.w};
            float bv[4] = {b4.x, b4.y, b4.z, b4.w};
            #pragma unroll
            for (int i = 0; i < 4; i++)
                #pragma unroll
                for (int j = 0; j < 4; j++)
                    acc[i][j] += av[i] * bv[j];
        }
        __syncthreads();
    }
    uint32_t* ph = (w == 0) ? g_qh[b] : ((w == 1) ? g_kh[b] : g_vh[b]);
    uint32_t* pl = (w == 0) ? g_ql[b] : ((w == 1) ? g_kl[b] : g_vl[b]);
    #pragma unroll
    for (int i = 0; i < 4; i++) {
        int m = m0 + ty * 4 + i;
        #pragma unroll
        for (int j = 0; j < 4; j++) {
            int n = n0 + tx * 4 + j;
            float val = acc[i][j];
            uint32_t hi, lo;
            f2tf2(val, hi, lo);
            ph[(size_t)m * T_ + n] = hi;
            pl[(size_t)m * T_ + n] = lo;
            if (w == 2) g_v[b][(size_t)m * T_ + n] = val;
        }
    }
}

// K2: per-head scores via 3xTF32 mma, 2-stage cp.async pipeline.
// Block tile 128x128, BK=16, 8 warps as 2(m)x4(n).  grid (8, 8, 16)
#define SC_PLANE (16 * 136)
#define SC_SMEM  (2 * 4 * SC_PLANE * 4)    // 69632 bytes
__global__ void __launch_bounds__(256) k_score_mma() {
    extern __shared__ uint32_t sm[];
    int z = blockIdx.z;
    int b = z >> 2, h = z & 3;
    const uint32_t* Aph = g_qh[b] + h * D_ * T_;   // [d][q]
    const uint32_t* Apl = g_ql[b] + h * D_ * T_;
    const uint32_t* Bph = g_kh[b] + h * D_ * T_;   // [d][t]
    const uint32_t* Bpl = g_kl[b] + h * D_ * T_;
    float* Cm = g_s[z];
    const int m0 = blockIdx.y * 128;
    const int n0 = blockIdx.x * 128;

    float acc[4][4][4] = {};
    const int tid = threadIdx.x;
    const int wid = tid >> 5, lane = tid & 31;
    const int wm = wid >> 2, wn = wid & 3;
    const int g = lane >> 2, t = lane & 3;
    const int kk = tid >> 5;     // 0..7
    const int mm = lane * 4;     // 0..124

    auto issue = [&](int s, int k0) {
        const size_t r0 = (size_t)(k0 + kk) * T_;
        const size_t r8 = (size_t)(k0 + kk + 8) * T_;
        uint32_t* base = sm + s * 4 * SC_PLANE;
        cpasync16(base + kk * 136 + mm,                    Aph + r0 + m0 + mm);
        cpasync16(base + (kk + 8) * 136 + mm,              Aph + r8 + m0 + mm);
        cpasync16(base + SC_PLANE + kk * 136 + mm,         Apl + r0 + m0 + mm);
        cpasync16(base + SC_PLANE + (kk + 8) * 136 + mm,   Apl + r8 + m0 + mm);
        cpasync16(base + 2 * SC_PLANE + kk * 136 + mm,     Bph + r0 + n0 + mm);
        cpasync16(base + 2 * SC_PLANE + (kk + 8) * 136 + mm, Bph + r8 + n0 + mm);
        cpasync16(base + 3 * SC_PLANE + kk * 136 + mm,     Bpl + r0 + n0 + mm);
        cpasync16(base + 3 * SC_PLANE + (kk + 8) * 136 + mm, Bpl + r8 + n0 + mm);
        CP_COMMIT();
    };

    issue(0, 0);
    #pragma unroll
    for (int c = 0; c < 4; c++) {
        const int s = c & 1;
        CP_WAIT0();
        __syncthreads();
        if (c < 3) issue(s ^ 1, (c + 1) * 16);

        const uint32_t* Ah_ = sm + s * 4 * SC_PLANE;
        const uint32_t* Al_ = Ah_ + SC_PLANE;
        const uint32_t* Bh_ = Ah_ + 2 * SC_PLANE;
        const uint32_t* Bl_ = Ah_ + 3 * SC_PLANE;

        #pragma unroll
        for (int ks = 0; ks < 2; ks++) {
            const int kb = ks * 8;
            uint32_t afh[4][4], afl[4][4], bfh[4][2], bfl[4][2];
            #pragma unroll
            for (int mf = 0; mf < 4; mf++) {
                int row = wm * 64 + mf * 16;
                afh[mf][0] = Ah_[(kb + t) * 136 + row + g];
                afh[mf][1] = Ah_[(kb + t) * 136 + row + g + 8];
                afh[mf][2] = Ah_[(kb + t + 4) * 136 + row + g];
                afh[mf][3] = Ah_[(kb + t + 4) * 136 + row + g + 8];
                afl[mf][0] = Al_[(kb + t) * 136 + row + g];
                afl[mf][1] = Al_[(kb + t) * 136 + row + g + 8];
                afl[mf][2] = Al_[(kb + t + 4) * 136 + row + g];
                afl[mf][3] = Al_[(kb + t + 4) * 136 + row + g + 8];
            }
            #pragma unroll
            for (int nf = 0; nf < 4; nf++) {
                int col = wn * 32 + nf * 8;
                bfh[nf][0] = Bh_[(kb + t) * 136 + col + g];
                bfh[nf][1] = Bh_[(kb + t + 4) * 136 + col + g];
                bfl[nf][0] = Bl_[(kb + t) * 136 + col + g];
                bfl[nf][1] = Bl_[(kb + t + 4) * 136 + col + g];
            }
            #pragma unroll
            for (int mf = 0; mf < 4; mf++)
                #pragma unroll
                for (int nf = 0; nf < 4; nf++) {
                    mma_tf32(acc[mf][nf], afh[mf][0], afh[mf][1], afh[mf][2], afh[mf][3],
                             bfl[nf][0], bfl[nf][1]);
                    mma_tf32(acc[mf][nf], afl[mf][0], afl[mf][1], afl[mf][2], afl[mf][3],
                             bfh[nf][0], bfh[nf][1]);
                    mma_tf32(acc[mf][nf], afh[mf][0], afh[mf][1], afh[mf][2], afh[mf][3],
                             bfh[nf][0], bfh[nf][1]);
                }
        }
        __syncthreads();
    }

    const float alpha = 0.125f;
    #pragma unroll
    for (int mf = 0; mf < 4; mf++) {
        int r0 = m0 + wm * 64 + mf * 16 + g;
        #pragma unroll
        for (int nf = 0; nf < 4; nf++) {
            int cc = n0 + wn * 32 + nf * 8 + 2 * t;
            float2 lo = make_float2(alpha * acc[mf][nf][0], alpha * acc[mf][nf][1]);
            float2 hi = make_float2(alpha * acc[mf][nf][2], alpha * acc[mf][nf][3]);
            *(float2*)&Cm[(size_t)r0 * T_ + cc]       = lo;
            *(float2*)&Cm[(size_t)(r0 + 8) * T_ + cc] = hi;
        }
    }
}

// vsum[b][c] = sum_t v[b][c][t]
__global__ void k_vsum() {
    __shared__ float red[8];
    int b = blockIdx.x >> 8, c = blockIdx.x & 255;
    const float* row = g_v[b] + c * T_;
    float s = 0.f;
    for (int i = threadIdx.x; i < T_; i += 256) s += row[i];
    s = blkReduceSum(s, red);
    if (threadIdx.x == 0) g_vsum[b][c] = s;
}

// K3: head-mix + softmax + per-row sum(a^2). grid (B*T), 256 thr (float4 lanes)
__global__ void __launch_bounds__(256) k_softmax(const float* __restrict__ w_head) {
    __shared__ float rows[NH_][T_];
    __shared__ float red[8];
    int b = blockIdx.x >> 10, qq = blockIdx.x & 1023;
    const int tid = threadIdx.x;

    #pragma unroll
    for (int h = 0; h < NH_; h++)
        ((float4*)rows[h])[tid] = ((const float4*)(g_s[b * NH_ + h] + (size_t)qq * T_))[tid];
    __syncthreads();

    float wh[NH_][NH_];
    #pragma unroll
    for (int g = 0; g < NH_; g++)
        #pragma unroll
        for (int h = 0; h < NH_; h++)
            wh[g][h] = w_head[g * NH_ + h];

    for (int g = 0; g < NH_; g++) {
        float4 r0 = ((const float4*)rows[0])[tid];
        float4 r1 = ((const float4*)rows[1])[tid];
        float4 r2 = ((const float4*)rows[2])[tid];
        float4 r3 = ((const float4*)rows[3])[tid];
        float m[4];
        m[0] = wh[g][0] * r0.x + wh[g][1] * r1.x + wh[g][2] * r2.x + wh[g][3] * r3.x;
        m[1] = wh[g][0] * r0.y + wh[g][1] * r1.y + wh[g][2] * r2.y + wh[g][3] * r3.y;
        m[2] = wh[g][0] * r0.z + wh[g][1] * r1.z + wh[g][2] * r2.z + wh[g][3] * r3.z;
        m[3] = wh[g][0] * r0.w + wh[g][1] * r1.w + wh[g][2] * r2.w + wh[g][3] * r3.w;
        float mx = fmaxf(fmaxf(m[0], m[1]), fmaxf(m[2], m[3]));
        mx = blkReduceMax(mx, red);
        float e[4], s = 0.f;
        #pragma unroll
        for (int j = 0; j < 4; j++) { e[j] = __expf(m[j] - mx); s += e[j]; }
        s = blkReduceSum(s, red);
        float inv = 1.0f / s;
        float4 a4 = make_float4(e[0] * inv, e[1] * inv, e[2] * inv, e[3] * inv);
        ((float4*)(g_a[b * NH_ + g] + (size_t)qq * T_))[tid] = a4;
        float sq = a4.x * a4.x + a4.y * a4.y + a4.z * a4.z + a4.w * a4.w;
        sq = blkReduceSum(sq, red);
        if (tid == 0) g_rowsq[b * NH_ + g][qq] = sq;
        __syncthreads();
    }
}

// reduce rowsq -> ssq
__global__ void k_ssq() {
    __shared__ float red[8];
    int g = blockIdx.x;
    float s = 0.f;
    for (int i = threadIdx.x; i < T_; i += 256) s += g_rowsq[g][i];
    s = blkReduceSum(s, red);
    if (threadIdx.x == 0) g_ssq[g] = s;
}

// K4: A.V via 3xTF32 mma, 2-stage pipeline (A: LDG->cvt->STS, V: cp.async).
// Block tile 128(m) x 64(n), BK=16, 8 warps as 4(m)x2(n).  grid (8, 16)
#define AV_PA (128 * 20)
#define AV_PB (64 * 20)
#define AV_SS (2 * AV_PA + 2 * AV_PB)      // words per stage
#define AV_SMEM (2 * AV_SS * 4)            // 61440 bytes
__global__ void __launch_bounds__(256) k_av_mma(const float* __restrict__ gamma,
                                                const float* __restrict__ beta) {
    extern __shared__ uint32_t sm[];
    int z = blockIdx.y;
    int b = z >> 2, h = z & 3;
    const float* A = g_a[z];                        // [q][t]
    const uint32_t* Vph = g_vh[b] + h * D_ * T_;    // [d][t]
    const uint32_t* Vpl = g_vl[b] + h * D_ * T_;
    const int m0 = blockIdx.x * 128;

    float acc[2][4][4] = {};
    const int tid = threadIdx.x;
    const int wid = tid >> 5, lane = tid & 31;
    const int wm = wid >> 1, wn = wid & 1;
    const int g = lane >> 2, t = lane & 3;
    const int rowA = tid >> 1, halfA = tid & 1;     // A loader coords
    const int rowV = tid >> 2, qV = tid & 3;        // V loader coords

    auto sts_a = [&](int s, float4 v0, float4 v1) {
        uint32_t h4[8], l4[8];
        f2tf2(v0.x, h4[0], l4[0]);  f2tf2(v0.y, h4[1], l4[1]);
        f2tf2(v0.z, h4[2], l4[2]);  f2tf2(v0.w, h4[3], l4[3]);
        f2tf2(v1.x, h4[4], l4[4]);  f2tf2(v1.y, h4[5], l4[5]);
        f2tf2(v1.z, h4[6], l4[6]);  f2tf2(v1.w, h4[7], l4[7]);
        uint32_t* Ah_ = sm + s * AV_SS;
        uint32_t* Al_ = Ah_ + AV_PA;
        int cb = rowA * 20 + halfA * 8;
        *(uint4*)&Ah_[cb]     = *(uint4*)&h4[0];
        *(uint4*)&Ah_[cb + 4] = *(uint4*)&h4[4];
        *(uint4*)&Al_[cb]     = *(uint4*)&l4[0];
        *(uint4*)&Al_[cb + 4] = *(uint4*)&l4[4];
    };
    auto issue_v = [&](int s, int k0) {
        uint32_t* Bh_ = sm + s * AV_SS + 2 * AV_PA;
        uint32_t* Bl_ = Bh_ + AV_PB;
        const size_t off = (size_t)rowV * T_ + k0 + qV * 4;
        cpasync16(Bh_ + rowV * 20 + qV * 4, Vph + off);
        cpasync16(Bl_ + rowV * 20 + qV * 4, Vpl + off);
        CP_COMMIT();
    };

    {   // prologue: stage 0
        const float* src = &A[(size_t)(m0 + rowA) * T_ + halfA * 8];
        sts_a(0, *(const float4*)src, *(const float4*)(src + 4));
        issue_v(0, 0);
    }

    for (int c = 0; c < 64; c++) {
        const int s = c & 1;
        CP_WAIT0();
        __syncthreads();
        const bool pf = (c + 1 < 64);
        float4 va0, va1;
        if (pf) {
            const float* src = &A[(size_t)(m0 + rowA) * T_ + (c + 1) * 16 + halfA * 8];
            va0 = *(const float4*)src;
            va1 = *(const float4*)(src + 4);
            issue_v(s ^ 1, (c + 1) * 16);
        }

        const uint32_t* Ah_ = sm + s * AV_SS;
        const uint32_t* Al_ = Ah_ + AV_PA;
        const uint32_t* Bh_ = Ah_ + 2 * AV_PA;
        const uint32_t* Bl_ = Bh_ + AV_PB;

        #pragma unroll
        for (int ks = 0; ks < 2; ks++) {
            const int kb = ks * 8;
            uint32_t afh[2][4], afl[2][4], bfh[4][2], bfl[4][2];
            #pragma unroll
            for (int mf = 0; mf < 2; mf++) {
                int row = wm * 32 + mf * 16;
                afh[mf][0] = Ah_[(row + g) * 20 + kb + t];
                afh[mf][1] = Ah_[(row + g + 8) * 20 + kb + t];
                afh[mf][2] = Ah_[(row + g) * 20 + kb + t + 4];
                afh[mf][3] = Ah_[(row + g + 8) * 20 + kb + t + 4];
                afl[mf][0] = Al_[(row + g) * 20 + kb + t];
                afl[mf][1] = Al_[(row + g + 8) * 20 + kb + t];
                afl[mf][2] = Al_[(row + g) * 20 + kb + t + 4];
                afl[mf][3] = Al_[(row + g + 8) * 20 + kb + t + 4];
            }
            #pragma unroll
            for (int nf = 0; nf < 4; nf++) {
                int col = wn * 32 + nf * 8;
                bfh[nf][0] = Bh_[(col + g) * 20 + kb + t];
                bfh[nf][1] = Bh_[(col + g) * 20 + kb + t + 4];
                bfl[nf][0] = Bl_[(col + g) * 20 + kb + t];
                bfl[nf][1] = Bl_[(col + g) * 20 + kb + t + 4];
            }
            #pragma unroll
            for (int mf = 0; mf < 2; mf++)
                #pragma unroll
                for (int nf = 0; nf < 4; nf++) {
                    mma_tf32(acc[mf][nf], afh[mf][0], afh[mf][1], afh[mf][2], afh[mf][3],
                             bfl[nf][0], bfl[nf][1]);
                    mma_tf32(acc[mf][nf], afl[mf][0], afl[mf][1], afl[mf][2], afl[mf][3],
                             bfh[nf][0], bfh[nf][1]);
                    mma_tf32(acc[mf][nf], afh[mf][0], afh[mf][1], afh[mf][2], afh[mf][3],
                             bfh[nf][0], bfh[nf][1]);
                }
        }
        if (pf) sts_a(s ^ 1, va0, va1);
    }

    // fold InstanceNorm: mean = 1/T exactly; var = ssq/T^2 - mu^2
    const float mu  = 1.0f / (float)T_;
    const float var = g_ssq[z] * (1.0f / ((float)T_ * (float)T_)) - mu * mu;
    const float invs = rsqrtf(var + EPS_);
    const float c1 = gamma[h] * invs;
    const float c0 = beta[h] - c1 * mu;

    #pragma unroll
    for (int mf = 0; mf < 2; mf++) {
        #pragma unroll
        for (int rr = 0; rr < 2; rr++) {
            int q = m0 + wm * 32 + mf * 16 + g + rr * 8;
            int xrow  = h * 256 + (q >> 2);
            int cbase = (q & 3) * 64;
            #pragma unroll
            for (int nf = 0; nf < 4; nf++) {
                int d = wn * 32 + nf * 8 + 2 * t;
                float vs0 = g_vsum[b][h * D_ + d];
                float vs1 = g_vsum[b][h * D_ + d + 1];
                float o0 = c1 * acc[mf][nf][rr * 2]     + c0 * vs0;
                float o1 = c1 * acc[mf][nf][rr * 2 + 1] + c0 * vs1;
                *(float2*)&g_x2[b][(size_t)xrow * C_ + cbase + d] = make_float2(o0, o1);
            }
        }
    }
}

// K5: NT GEMM  y[o,t'] = sum_c wp[o,c] * X[t',c] + bias[o]
__global__ void __launch_bounds__(256) k_proj(const float* __restrict__ wp,
                                              const float* __restrict__ bp,
                                              float* __restrict__ out) {
    int b = blockIdx.z;
    int m0 = blockIdx.y * 64;
    int n0 = blockIdx.x * 64;
    __shared__ float Ast[16][68];
    __shared__ float Bst[16][68];
    float acc[4][4] = {};
    const int tid = threadIdx.x;
    const int lk = tid & 15, lr = tid >> 4;
    const int ty = tid >> 4, tx = tid & 15;
    const float* X = g_x2[b];
    for (int k0 = 0; k0 < C_; k0 += 16) {
        #pragma unroll
        for (int p = 0; p < 4; p++) {
            Ast[lk][lr + p * 16] = wp[(m0 + lr + p * 16) * C_ + k0 + lk];
            Bst[lk][lr + p * 16] = X[(n0 + lr + p * 16) * C_ + k0 + lk];
        }
        __syncthreads();
        #pragma unroll
        for (int k = 0; k < 16; k++) {
            float4 a4 = *(const float4*)&Ast[k][ty * 4];
            float4 b4 = *(const float4*)&Bst[k][tx * 4];
            float av[4] = {a4.x, a4.y, a4.z, a4.w};
            float bv[4] = {b4.x, b4.y, b4.z, b4.w};
            #pragma unroll
            for (int i = 0; i < 4; i++)
                #pragma unroll
                for (int j = 0; j < 4; j++)
                    acc[i][j] += av[i] * bv[j];
        }
        __syncthreads();
    }
    #pragma unroll
    for (int i = 0; i < 4; i++) {
        int o = m0 + ty * 4 + i;
        float bias = bp[o];
        #pragma unroll
        for (int j = 0; j < 4; j++)
            out[(size_t)b * C_ * T_ + o * T_ + n0 + tx * 4 + j] = acc[i][j] + bias;
    }
}

// ------------------------- launch -------------------------
extern "C" void kernel_launch(void* const* d_in, const int* in_sizes, int n_in,
                              void* d_out, int out_size) {
    const float* x      = (const float*)d_in[0];
    const float* wq     = (const float*)d_in[1];
    const float* wk     = (const float*)d_in[2];
    const float* wv     = (const float*)d_in[3];
    const float* w_head = (const float*)d_in[4];
    const float* gamma  = (const float*)d_in[5];
    const float* beta   = (const float*)d_in[6];
    const float* w_proj = (const float*)d_in[7];
    const float* b_proj = (const float*)d_in[8];
    float* out = (float*)d_out;

    static bool attr_set = false;
    if (!attr_set) {
        cudaFuncSetAttribute(k_score_mma, cudaFuncAttributeMaxDynamicSharedMemorySize, SC_SMEM);
        cudaFuncSetAttribute(k_av_mma, cudaFuncAttributeMaxDynamicSharedMemorySize, AV_SMEM);
        attr_set = true;
    }

    k_transpose<<<dim3(8, 8, 3), dim3(32, 32)>>>(wq, wk, wv);
    k_qkv<<<dim3(16, 4, 12), 256>>>(x);
    k_vsum<<<B_ * C_, 256>>>();
    k_score_mma<<<dim3(8, 8, 16), 256, SC_SMEM>>>();
    k_softmax<<<B_ * T_, 256>>>(w_head);
    k_ssq<<<B_ * NH_, 256>>>();
    k_av_mma<<<dim3(8, 16), 256, AV_SMEM>>>(gamma, beta);
    k_proj<<<dim3(16, 4, 4), 256>>>(w_proj, b_proj, out);
}

// round 8
// speedup vs baseline: 1.5228x; 1.1063x over previous
#include <cuda_runtime.h>
#include <cstdint>

#define B_  4
#define C_  256
#define NH_ 4
#define D_  64
#define T_  1024
#define EPS_ 1e-5f

// ------------------------- static scratch (no allocs) -------------------------
__device__ uint32_t g_wth[3][C_ * C_];        // wt hi/lo planes  [c][o]
__device__ uint32_t g_wtl[3][C_ * C_];
__device__ uint32_t g_xh[B_][C_ * T_];        // x hi/lo planes   [c][t]
__device__ uint32_t g_xl[B_][C_ * T_];
__device__ float g_v[B_][C_ * T_];            // fp32 V (for vsum)
__device__ uint32_t g_qh[B_][C_ * T_];        // q/k/v tf32 hi/lo planes
__device__ uint32_t g_ql[B_][C_ * T_];
__device__ uint32_t g_kh[B_][C_ * T_];
__device__ uint32_t g_kl[B_][C_ * T_];
__device__ uint32_t g_vh[B_][C_ * T_];
__device__ uint32_t g_vl[B_][C_ * T_];
__device__ float g_s[B_ * NH_][T_ * T_];      // raw per-head scores (scaled)
__device__ float g_a[B_ * NH_][T_ * T_];      // softmax(mixed scores)
__device__ float g_rowsq[B_ * NH_][T_];       // per-row sum(a^2)
__device__ float g_ssq[B_ * NH_];             // total sum(a^2) per (b,g)
__device__ float g_vsum[B_][C_];              // sum over t of v
__device__ float g_x2[B_][T_ * C_];           // reshaped attention output [t'][c']

// ------------------------- mma / async helpers -------------------------
__device__ __forceinline__ uint32_t f2tf(float f) {
    uint32_t u;
    asm("cvt.rna.tf32.f32 %0, %1;" : "=r"(u) : "f"(f));
    return u;
}

__device__ __forceinline__ void f2tf2(float f, uint32_t& hi, uint32_t& lo) {
    hi = f2tf(f);
    lo = f2tf(f - __uint_as_float(hi));
}

__device__ __forceinline__ void mma_tf32(float c[4],
                                         uint32_t a0, uint32_t a1, uint32_t a2, uint32_t a3,
                                         uint32_t b0, uint32_t b1) {
    asm volatile(
        "mma.sync.aligned.m16n8k8.row.col.f32.tf32.tf32.f32 "
        "{%0,%1,%2,%3},{%4,%5,%6,%7},{%8,%9},{%0,%1,%2,%3};\n"
        : "+f"(c[0]), "+f"(c[1]), "+f"(c[2]), "+f"(c[3])
        : "r"(a0), "r"(a1), "r"(a2), "r"(a3), "r"(b0), "r"(b1));
}

__device__ __forceinline__ void cpasync16(uint32_t* smem_dst, const uint32_t* gmem_src) {
    uint32_t s = (uint32_t)__cvta_generic_to_shared(smem_dst);
    asm volatile("cp.async.cg.shared.global [%0], [%1], 16;\n" :: "r"(s), "l"(gmem_src));
}
#define CP_COMMIT() asm volatile("cp.async.commit_group;\n")
#define CP_WAIT0()  asm volatile("cp.async.wait_group 0;\n")

// ------------------------- reductions -------------------------
__device__ __forceinline__ float blkReduceSum(float v, float* red) {
    #pragma unroll
    for (int o = 16; o > 0; o >>= 1) v += __shfl_xor_sync(0xffffffffu, v, o);
    if ((threadIdx.x & 31) == 0) red[threadIdx.x >> 5] = v;
    __syncthreads();
    float s = red[0];
    #pragma unroll
    for (int i = 1; i < 8; i++) s += red[i];
    __syncthreads();
    return s;
}

__device__ __forceinline__ float blkReduceMax(float v, float* red) {
    #pragma unroll
    for (int o = 16; o > 0; o >>= 1) v = fmaxf(v, __shfl_xor_sync(0xffffffffu, v, o));
    if ((threadIdx.x & 31) == 0) red[threadIdx.x >> 5] = v;
    __syncthreads();
    float s = red[0];
    #pragma unroll
    for (int i = 1; i < 8; i++) s = fmaxf(s, red[i]);
    __syncthreads();
    return s;
}

// ------------------------- weight transpose -> tf32 planes -------------------------
__global__ void k_transpose(const float* __restrict__ wq,
                            const float* __restrict__ wk,
                            const float* __restrict__ wv) {
    __shared__ float tile[32][33];
    const float* src = (blockIdx.z == 0) ? wq : ((blockIdx.z == 1) ? wk : wv);
    int c = blockIdx.x * 32 + threadIdx.x;
    int o = blockIdx.y * 32 + threadIdx.y;
    tile[threadIdx.y][threadIdx.x] = src[o * C_ + c];
    __syncthreads();
    int oo = blockIdx.y * 32 + threadIdx.x;
    int cc = blockIdx.x * 32 + threadIdx.y;
    float val = tile[threadIdx.x][threadIdx.y];
    uint32_t hi, lo;
    f2tf2(val, hi, lo);
    g_wth[blockIdx.z][cc * C_ + oo] = hi;
    g_wtl[blockIdx.z][cc * C_ + oo] = lo;
}

// x -> tf32 hi/lo planes. B*C*T = 1,048,576 floats = 262,144 float4 -> grid 1024 x 256.
__global__ void k_xsplit(const float* __restrict__ x) {
    size_t i = (size_t)blockIdx.x * 256 + threadIdx.x;
    float4 v = ((const float4*)x)[i];
    uint32_t h[4], l[4];
    f2tf2(v.x, h[0], l[0]);
    f2tf2(v.y, h[1], l[1]);
    f2tf2(v.z, h[2], l[2]);
    f2tf2(v.w, h[3], l[3]);
    ((uint4*)&g_xh[0][0])[i] = *(uint4*)h;
    ((uint4*)&g_xl[0][0])[i] = *(uint4*)l;
}

// K1: q/k/v = Wt^T x via 3xTF32 mma, 2-stage cp.async pipeline.
// Block tile 128(o) x 128(t), BK=16, K=256 (16 chunks). grid (8, 2, 12)  z=w*4+b
#define SC_PLANE (16 * 136)
#define SC_SMEM  (2 * 4 * SC_PLANE * 4)    // 69632 bytes
__global__ void __launch_bounds__(256, 2) k_qkv_mma() {
    extern __shared__ uint32_t sm[];
    int z = blockIdx.z;
    int w = z >> 2, b = z & 3;
    const uint32_t* Aph = g_wth[w];      // [c][o], ld C_
    const uint32_t* Apl = g_wtl[w];
    const uint32_t* Bph = g_xh[b];       // [c][t], ld T_
    const uint32_t* Bpl = g_xl[b];
    const int m0 = blockIdx.y * 128;
    const int n0 = blockIdx.x * 128;

    float acc[4][4][4] = {};
    const int tid = threadIdx.x;
    const int wid = tid >> 5, lane = tid & 31;
    const int wm = wid >> 2, wn = wid & 3;
    const int g = lane >> 2, t = lane & 3;
    const int kk = tid >> 5;
    const int mm = lane * 4;

    auto issue = [&](int s, int k0) {
        const size_t a0 = (size_t)(k0 + kk) * C_;
        const size_t a8 = (size_t)(k0 + kk + 8) * C_;
        const size_t r0 = (size_t)(k0 + kk) * T_;
        const size_t r8 = (size_t)(k0 + kk + 8) * T_;
        uint32_t* base = sm + s * 4 * SC_PLANE;
        cpasync16(base + kk * 136 + mm,                      Aph + a0 + m0 + mm);
        cpasync16(base + (kk + 8) * 136 + mm,                Aph + a8 + m0 + mm);
        cpasync16(base + SC_PLANE + kk * 136 + mm,           Apl + a0 + m0 + mm);
        cpasync16(base + SC_PLANE + (kk + 8) * 136 + mm,     Apl + a8 + m0 + mm);
        cpasync16(base + 2 * SC_PLANE + kk * 136 + mm,       Bph + r0 + n0 + mm);
        cpasync16(base + 2 * SC_PLANE + (kk + 8) * 136 + mm, Bph + r8 + n0 + mm);
        cpasync16(base + 3 * SC_PLANE + kk * 136 + mm,       Bpl + r0 + n0 + mm);
        cpasync16(base + 3 * SC_PLANE + (kk + 8) * 136 + mm, Bpl + r8 + n0 + mm);
        CP_COMMIT();
    };

    issue(0, 0);
    for (int c = 0; c < 16; c++) {
        const int s = c & 1;
        CP_WAIT0();
        __syncthreads();
        if (c < 15) issue(s ^ 1, (c + 1) * 16);

        const uint32_t* Ah_ = sm + s * 4 * SC_PLANE;
        const uint32_t* Al_ = Ah_ + SC_PLANE;
        const uint32_t* Bh_ = Ah_ + 2 * SC_PLANE;
        const uint32_t* Bl_ = Ah_ + 3 * SC_PLANE;

        #pragma unroll
        for (int ks = 0; ks < 2; ks++) {
            const int kb = ks * 8;
            uint32_t afh[4][4], afl[4][4], bfh[4][2], bfl[4][2];
            #pragma unroll
            for (int mf = 0; mf < 4; mf++) {
                int row = wm * 64 + mf * 16;
                afh[mf][0] = Ah_[(kb + t) * 136 + row + g];
                afh[mf][1] = Ah_[(kb + t) * 136 + row + g + 8];
                afh[mf][2] = Ah_[(kb + t + 4) * 136 + row + g];
                afh[mf][3] = Ah_[(kb + t + 4) * 136 + row + g + 8];
                afl[mf][0] = Al_[(kb + t) * 136 + row + g];
                afl[mf][1] = Al_[(kb + t) * 136 + row + g + 8];
                afl[mf][2] = Al_[(kb + t + 4) * 136 + row + g];
                afl[mf][3] = Al_[(kb + t + 4) * 136 + row + g + 8];
            }
            #pragma unroll
            for (int nf = 0; nf < 4; nf++) {
                int col = wn * 32 + nf * 8;
                bfh[nf][0] = Bh_[(kb + t) * 136 + col + g];
                bfh[nf][1] = Bh_[(kb + t + 4) * 136 + col + g];
                bfl[nf][0] = Bl_[(kb + t) * 136 + col + g];
                bfl[nf][1] = Bl_[(kb + t + 4) * 136 + col + g];
            }
            #pragma unroll
            for (int mf = 0; mf < 4; mf++)
                #pragma unroll
                for (int nf = 0; nf < 4; nf++) {
                    mma_tf32(acc[mf][nf], afh[mf][0], afh[mf][1], afh[mf][2], afh[mf][3],
                             bfl[nf][0], bfl[nf][1]);
                    mma_tf32(acc[mf][nf], afl[mf][0], afl[mf][1], afl[mf][2], afl[mf][3],
                             bfh[nf][0], bfh[nf][1]);
                    mma_tf32(acc[mf][nf], afh[mf][0], afh[mf][1], afh[mf][2], afh[mf][3],
                             bfh[nf][0], bfh[nf][1]);
                }
        }
        __syncthreads();
    }

    uint32_t* ph = (w == 0) ? g_qh[b] : ((w == 1) ? g_kh[b] : g_vh[b]);
    uint32_t* pl = (w == 0) ? g_ql[b] : ((w == 1) ? g_kl[b] : g_vl[b]);
    #pragma unroll
    for (int mf = 0; mf < 4; mf++) {
        #pragma unroll
        for (int rr = 0; rr < 2; rr++) {
            int m = m0 + wm * 64 + mf * 16 + g + rr * 8;
            #pragma unroll
            for (int nf = 0; nf < 4; nf++) {
                int n = n0 + wn * 32 + nf * 8 + 2 * t;
                float v0 = acc[mf][nf][rr * 2];
                float v1 = acc[mf][nf][rr * 2 + 1];
                uint32_t h0, l0, h1, l1;
                f2tf2(v0, h0, l0);
                f2tf2(v1, h1, l1);
                *(uint2*)&ph[(size_t)m * T_ + n] = make_uint2(h0, h1);
                *(uint2*)&pl[(size_t)m * T_ + n] = make_uint2(l0, l1);
                if (w == 2)
                    *(float2*)&g_v[b][(size_t)m * T_ + n] = make_float2(v0, v1);
            }
        }
    }
}

// K2: per-head scores via 3xTF32 mma, 2-stage cp.async pipeline.
// Block tile 128x128, BK=16, 8 warps as 2(m)x4(n).  grid (8, 8, 16)
__global__ void __launch_bounds__(256, 2) k_score_mma() {
    extern __shared__ uint32_t sm[];
    int z = blockIdx.z;
    int b = z >> 2, h = z & 3;
    const uint32_t* Aph = g_qh[b] + h * D_ * T_;   // [d][q]
    const uint32_t* Apl = g_ql[b] + h * D_ * T_;
    const uint32_t* Bph = g_kh[b] + h * D_ * T_;   // [d][t]
    const uint32_t* Bpl = g_kl[b] + h * D_ * T_;
    float* Cm = g_s[z];
    const int m0 = blockIdx.y * 128;
    const int n0 = blockIdx.x * 128;

    float acc[4][4][4] = {};
    const int tid = threadIdx.x;
    const int wid = tid >> 5, lane = tid & 31;
    const int wm = wid >> 2, wn = wid & 3;
    const int g = lane >> 2, t = lane & 3;
    const int kk = tid >> 5;
    const int mm = lane * 4;

    auto issue = [&](int s, int k0) {
        const size_t r0 = (size_t)(k0 + kk) * T_;
        const size_t r8 = (size_t)(k0 + kk + 8) * T_;
        uint32_t* base = sm + s * 4 * SC_PLANE;
        cpasync16(base + kk * 136 + mm,                      Aph + r0 + m0 + mm);
        cpasync16(base + (kk + 8) * 136 + mm,                Aph + r8 + m0 + mm);
        cpasync16(base + SC_PLANE + kk * 136 + mm,           Apl + r0 + m0 + mm);
        cpasync16(base + SC_PLANE + (kk + 8) * 136 + mm,     Apl + r8 + m0 + mm);
        cpasync16(base + 2 * SC_PLANE + kk * 136 + mm,       Bph + r0 + n0 + mm);
        cpasync16(base + 2 * SC_PLANE + (kk + 8) * 136 + mm, Bph + r8 + n0 + mm);
        cpasync16(base + 3 * SC_PLANE + kk * 136 + mm,       Bpl + r0 + n0 + mm);
        cpasync16(base + 3 * SC_PLANE + (kk + 8) * 136 + mm, Bpl + r8 + n0 + mm);
        CP_COMMIT();
    };

    issue(0, 0);
    #pragma unroll
    for (int c = 0; c < 4; c++) {
        const int s = c & 1;
        CP_WAIT0();
        __syncthreads();
        if (c < 3) issue(s ^ 1, (c + 1) * 16);

        const uint32_t* Ah_ = sm + s * 4 * SC_PLANE;
        const uint32_t* Al_ = Ah_ + SC_PLANE;
        const uint32_t* Bh_ = Ah_ + 2 * SC_PLANE;
        const uint32_t* Bl_ = Ah_ + 3 * SC_PLANE;

        #pragma unroll
        for (int ks = 0; ks < 2; ks++) {
            const int kb = ks * 8;
            uint32_t afh[4][4], afl[4][4], bfh[4][2], bfl[4][2];
            #pragma unroll
            for (int mf = 0; mf < 4; mf++) {
                int row = wm * 64 + mf * 16;
                afh[mf][0] = Ah_[(kb + t) * 136 + row + g];
                afh[mf][1] = Ah_[(kb + t) * 136 + row + g + 8];
                afh[mf][2] = Ah_[(kb + t + 4) * 136 + row + g];
                afh[mf][3] = Ah_[(kb + t + 4) * 136 + row + g + 8];
                afl[mf][0] = Al_[(kb + t) * 136 + row + g];
                afl[mf][1] = Al_[(kb + t) * 136 + row + g + 8];
                afl[mf][2] = Al_[(kb + t + 4) * 136 + row + g];
                afl[mf][3] = Al_[(kb + t + 4) * 136 + row + g + 8];
            }
            #pragma unroll
            for (int nf = 0; nf < 4; nf++) {
                int col = wn * 32 + nf * 8;
                bfh[nf][0] = Bh_[(kb + t) * 136 + col + g];
                bfh[nf][1] = Bh_[(kb + t + 4) * 136 + col + g];
                bfl[nf][0] = Bl_[(kb + t) * 136 + col + g];
                bfl[nf][1] = Bl_[(kb + t + 4) * 136 + col + g];
            }
            #pragma unroll
            for (int mf = 0; mf < 4; mf++)
                #pragma unroll
                for (int nf = 0; nf < 4; nf++) {
                    mma_tf32(acc[mf][nf], afh[mf][0], afh[mf][1], afh[mf][2], afh[mf][3],
                             bfl[nf][0], bfl[nf][1]);
                    mma_tf32(acc[mf][nf], afl[mf][0], afl[mf][1], afl[mf][2], afl[mf][3],
                             bfh[nf][0], bfh[nf][1]);
                    mma_tf32(acc[mf][nf], afh[mf][0], afh[mf][1], afh[mf][2], afh[mf][3],
                             bfh[nf][0], bfh[nf][1]);
                }
        }
        __syncthreads();
    }

    const float alpha = 0.125f;
    #pragma unroll
    for (int mf = 0; mf < 4; mf++) {
        int r0 = m0 + wm * 64 + mf * 16 + g;
        #pragma unroll
        for (int nf = 0; nf < 4; nf++) {
            int cc = n0 + wn * 32 + nf * 8 + 2 * t;
            float2 lo = make_float2(alpha * acc[mf][nf][0], alpha * acc[mf][nf][1]);
            float2 hi = make_float2(alpha * acc[mf][nf][2], alpha * acc[mf][nf][3]);
            *(float2*)&Cm[(size_t)r0 * T_ + cc]       = lo;
            *(float2*)&Cm[(size_t)(r0 + 8) * T_ + cc] = hi;
        }
    }
}

// vsum[b][c] = sum_t v[b][c][t]
__global__ void k_vsum() {
    __shared__ float red[8];
    int b = blockIdx.x >> 8, c = blockIdx.x & 255;
    const float* row = g_v[b] + c * T_;
    float s = 0.f;
    for (int i = threadIdx.x; i < T_; i += 256) s += row[i];
    s = blkReduceSum(s, red);
    if (threadIdx.x == 0) g_vsum[b][c] = s;
}

// K3: head-mix + softmax + per-row sum(a^2). grid (B*T), 256 thr (float4 lanes)
__global__ void __launch_bounds__(256) k_softmax(const float* __restrict__ w_head) {
    __shared__ float rows[NH_][T_];
    __shared__ float red[8];
    int b = blockIdx.x >> 10, qq = blockIdx.x & 1023;
    const int tid = threadIdx.x;

    #pragma unroll
    for (int h = 0; h < NH_; h++)
        ((float4*)rows[h])[tid] = ((const float4*)(g_s[b * NH_ + h] + (size_t)qq * T_))[tid];
    __syncthreads();

    float wh[NH_][NH_];
    #pragma unroll
    for (int g = 0; g < NH_; g++)
        #pragma unroll
        for (int h = 0; h < NH_; h++)
            wh[g][h] = w_head[g * NH_ + h];

    for (int g = 0; g < NH_; g++) {
        float4 r0 = ((const float4*)rows[0])[tid];
        float4 r1 = ((const float4*)rows[1])[tid];
        float4 r2 = ((const float4*)rows[2])[tid];
        float4 r3 = ((const float4*)rows[3])[tid];
        float m[4];
        m[0] = wh[g][0] * r0.x + wh[g][1] * r1.x + wh[g][2] * r2.x + wh[g][3] * r3.x;
        m[1] = wh[g][0] * r0.y + wh[g][1] * r1.y + wh[g][2] * r2.y + wh[g][3] * r3.y;
        m[2] = wh[g][0] * r0.z + wh[g][1] * r1.z + wh[g][2] * r2.z + wh[g][3] * r3.z;
        m[3] = wh[g][0] * r0.w + wh[g][1] * r1.w + wh[g][2] * r2.w + wh[g][3] * r3.w;
        float mx = fmaxf(fmaxf(m[0], m[1]), fmaxf(m[2], m[3]));
        mx = blkReduceMax(mx, red);
        float e[4], s = 0.f;
        #pragma unroll
        for (int j = 0; j < 4; j++) { e[j] = __expf(m[j] - mx); s += e[j]; }
        s = blkReduceSum(s, red);
        float inv = 1.0f / s;
        float4 a4 = make_float4(e[0] * inv, e[1] * inv, e[2] * inv, e[3] * inv);
        ((float4*)(g_a[b * NH_ + g] + (size_t)qq * T_))[tid] = a4;
        float sq = a4.x * a4.x + a4.y * a4.y + a4.z * a4.z + a4.w * a4.w;
        sq = blkReduceSum(sq, red);
        if (tid == 0) g_rowsq[b * NH_ + g][qq] = sq;
        __syncthreads();
    }
}

// reduce rowsq -> ssq
__global__ void k_ssq() {
    __shared__ float red[8];
    int g = blockIdx.x;
    float s = 0.f;
    for (int i = threadIdx.x; i < T_; i += 256) s += g_rowsq[g][i];
    s = blkReduceSum(s, red);
    if (threadIdx.x == 0) g_ssq[g] = s;
}

// K4: A.V via 3xTF32 mma, 2-stage pipeline (A: LDG->cvt->STS, V: cp.async).
// Block tile 128(m) x 64(n), BK=16, 8 warps as 4(m)x2(n).  grid (8, 16)
#define AV_PA (128 * 20)
#define AV_PB (64 * 20)
#define AV_SS (2 * AV_PA + 2 * AV_PB)
#define AV_SMEM (2 * AV_SS * 4)            // 61440 bytes
__global__ void __launch_bounds__(256, 2) k_av_mma(const float* __restrict__ gamma,
                                                   const float* __restrict__ beta) {
    extern __shared__ uint32_t sm[];
    int z = blockIdx.y;
    int b = z >> 2, h = z & 3;
    const float* A = g_a[z];                        // [q][t]
    const uint32_t* Vph = g_vh[b] + h * D_ * T_;    // [d][t]
    const uint32_t* Vpl = g_vl[b] + h * D_ * T_;
    const int m0 = blockIdx.x * 128;

    float acc[2][4][4] = {};
    const int tid = threadIdx.x;
    const int wid = tid >> 5, lane = tid & 31;
    const int wm = wid >> 1, wn = wid & 1;
    const int g = lane >> 2, t = lane & 3;
    const int rowA = tid >> 1, halfA = tid & 1;
    const int rowV = tid >> 2, qV = tid & 3;

    auto sts_a = [&](int s, float4 v0, float4 v1) {
        uint32_t h4[8], l4[8];
        f2tf2(v0.x, h4[0], l4[0]);  f2tf2(v0.y, h4[1], l4[1]);
        f2tf2(v0.z, h4[2], l4[2]);  f2tf2(v0.w, h4[3], l4[3]);
        f2tf2(v1.x, h4[4], l4[4]);  f2tf2(v1.y, h4[5], l4[5]);
        f2tf2(v1.z, h4[6], l4[6]);  f2tf2(v1.w, h4[7], l4[7]);
        uint32_t* Ah_ = sm + s * AV_SS;
        uint32_t* Al_ = Ah_ + AV_PA;
        int cb = rowA * 20 + halfA * 8;
        *(uint4*)&Ah_[cb]     = *(uint4*)&h4[0];
        *(uint4*)&Ah_[cb + 4] = *(uint4*)&h4[4];
        *(uint4*)&Al_[cb]     = *(uint4*)&l4[0];
        *(uint4*)&Al_[cb + 4] = *(uint4*)&l4[4];
    };
    auto issue_v = [&](int s, int k0) {
        uint32_t* Bh_ = sm + s * AV_SS + 2 * AV_PA;
        uint32_t* Bl_ = Bh_ + AV_PB;
        const size_t off = (size_t)rowV * T_ + k0 + qV * 4;
        cpasync16(Bh_ + rowV * 20 + qV * 4, Vph + off);
        cpasync16(Bl_ + rowV * 20 + qV * 4, Vpl + off);
        CP_COMMIT();
    };

    {
        const float* src = &A[(size_t)(m0 + rowA) * T_ + halfA * 8];
        sts_a(0, *(const float4*)src, *(const float4*)(src + 4));
        issue_v(0, 0);
    }

    for (int c = 0; c < 64; c++) {
        const int s = c & 1;
        CP_WAIT0();
        __syncthreads();
        const bool pf = (c + 1 < 64);
        float4 va0, va1;
        if (pf) {
            const float* src = &A[(size_t)(m0 + rowA) * T_ + (c + 1) * 16 + halfA * 8];
            va0 = *(const float4*)src;
            va1 = *(const float4*)(src + 4);
            issue_v(s ^ 1, (c + 1) * 16);
        }

        const uint32_t* Ah_ = sm + s * AV_SS;
        const uint32_t* Al_ = Ah_ + AV_PA;
        const uint32_t* Bh_ = Ah_ + 2 * AV_PA;
        const uint32_t* Bl_ = Bh_ + AV_PB;

        #pragma unroll
        for (int ks = 0; ks < 2; ks++) {
            const int kb = ks * 8;
            uint32_t afh[2][4], afl[2][4], bfh[4][2], bfl[4][2];
            #pragma unroll
            for (int mf = 0; mf < 2; mf++) {
                int row = wm * 32 + mf * 16;
                afh[mf][0] = Ah_[(row + g) * 20 + kb + t];
                afh[mf][1] = Ah_[(row + g + 8) * 20 + kb + t];
                afh[mf][2] = Ah_[(row + g) * 20 + kb + t + 4];
                afh[mf][3] = Ah_[(row + g + 8) * 20 + kb + t + 4];
                afl[mf][0] = Al_[(row + g) * 20 + kb + t];
                afl[mf][1] = Al_[(row + g + 8) * 20 + kb + t];
                afl[mf][2] = Al_[(row + g) * 20 + kb + t + 4];
                afl[mf][3] = Al_[(row + g + 8) * 20 + kb + t + 4];
            }
            #pragma unroll
            for (int nf = 0; nf < 4; nf++) {
                int col = wn * 32 + nf * 8;
                bfh[nf][0] = Bh_[(col + g) * 20 + kb + t];
                bfh[nf][1] = Bh_[(col + g) * 20 + kb + t + 4];
                bfl[nf][0] = Bl_[(col + g) * 20 + kb + t];
                bfl[nf][1] = Bl_[(col + g) * 20 + kb + t + 4];
            }
            #pragma unroll
            for (int mf = 0; mf < 2; mf++)
                #pragma unroll
                for (int nf = 0; nf < 4; nf++) {
                    mma_tf32(acc[mf][nf], afh[mf][0], afh[mf][1], afh[mf][2], afh[mf][3],
                             bfl[nf][0], bfl[nf][1]);
                    mma_tf32(acc[mf][nf], afl[mf][0], afl[mf][1], afl[mf][2], afl[mf][3],
                             bfh[nf][0], bfh[nf][1]);
                    mma_tf32(acc[mf][nf], afh[mf][0], afh[mf][1], afh[mf][2], afh[mf][3],
                             bfh[nf][0], bfh[nf][1]);
                }
        }
        if (pf) sts_a(s ^ 1, va0, va1);
    }

    const float mu  = 1.0f / (float)T_;
    const float var = g_ssq[z] * (1.0f / ((float)T_ * (float)T_)) - mu * mu;
    const float invs = rsqrtf(var + EPS_);
    const float c1 = gamma[h] * invs;
    const float c0 = beta[h] - c1 * mu;

    #pragma unroll
    for (int mf = 0; mf < 2; mf++) {
        #pragma unroll
        for (int rr = 0; rr < 2; rr++) {
            int q = m0 + wm * 32 + mf * 16 + g + rr * 8;
            int xrow  = h * 256 + (q >> 2);
            int cbase = (q & 3) * 64;
            #pragma unroll
            for (int nf = 0; nf < 4; nf++) {
                int d = wn * 32 + nf * 8 + 2 * t;
                float vs0 = g_vsum[b][h * D_ + d];
                float vs1 = g_vsum[b][h * D_ + d + 1];
                float o0 = c1 * acc[mf][nf][rr * 2]     + c0 * vs0;
                float o1 = c1 * acc[mf][nf][rr * 2 + 1] + c0 * vs1;
                *(float2*)&g_x2[b][(size_t)xrow * C_ + cbase + d] = make_float2(o0, o1);
            }
        }
    }
}

// K5: NT GEMM  y[o,t'] = sum_c wp[o,c] * X[t',c] + bias[o]
__global__ void __launch_bounds__(256) k_proj(const float* __restrict__ wp,
                                              const float* __restrict__ bp,
                                              float* __restrict__ out) {
    int b = blockIdx.z;
    int m0 = blockIdx.y * 64;
    int n0 = blockIdx.x * 64;
    __shared__ float Ast[16][68];
    __shared__ float Bst[16][68];
    float acc[4][4] = {};
    const int tid = threadIdx.x;
    const int lk = tid & 15, lr = tid >> 4;
    const int ty = tid >> 4, tx = tid & 15;
    const float* X = g_x2[b];
    for (int k0 = 0; k0 < C_; k0 += 16) {
        #pragma unroll
        for (int p = 0; p < 4; p++) {
            Ast[lk][lr + p * 16] = wp[(m0 + lr + p * 16) * C_ + k0 + lk];
            Bst[lk][lr + p * 16] = X[(n0 + lr + p * 16) * C_ + k0 + lk];
        }
        __syncthreads();
        #pragma unroll
        for (int k = 0; k < 16; k++) {
            float4 a4 = *(const float4*)&Ast[k][ty * 4];
            float4 b4 = *(const float4*)&Bst[k][tx * 4];
            float av[4] = {a4.x, a4.y, a4.z, a4.w};
            float bv[4] = {b4.x, b4.y, b4.z, b4.w};
            #pragma unroll
            for (int i = 0; i < 4; i++)
                #pragma unroll
                for (int j = 0; j < 4; j++)
                    acc[i][j] += av[i] * bv[j];
        }
        __syncthreads();
    }
    #pragma unroll
    for (int i = 0; i < 4; i++) {
        int o = m0 + ty * 4 + i;
        float bias = bp[o];
        #pragma unroll
        for (int j = 0; j < 4; j++)
            out[(size_t)b * C_ * T_ + o * T_ + n0 + tx * 4 + j] = acc[i][j] + bias;
    }
}

// ------------------------- launch -------------------------
extern "C" void kernel_launch(void* const* d_in, const int* in_sizes, int n_in,
                              void* d_out, int out_size) {
    const float* x      = (const float*)d_in[0];
    const float* wq     = (const float*)d_in[1];
    const float* wk     = (const float*)d_in[2];
    const float* wv     = (const float*)d_in[3];
    const float* w_head = (const float*)d_in[4];
    const float* gamma  = (const float*)d_in[5];
    const float* beta   = (const float*)d_in[6];
    const float* w_proj = (const float*)d_in[7];
    const float* b_proj = (const float*)d_in[8];
    float* out = (float*)d_out;

    // idempotent, deterministic on every call (no static guards per harness rules)
    cudaFuncSetAttribute(k_qkv_mma, cudaFuncAttributeMaxDynamicSharedMemorySize, SC_SMEM);
    cudaFuncSetAttribute(k_score_mma, cudaFuncAttributeMaxDynamicSharedMemorySize, SC_SMEM);
    cudaFuncSetAttribute(k_av_mma, cudaFuncAttributeMaxDynamicSharedMemorySize, AV_SMEM);

    k_transpose<<<dim3(8, 8, 3), dim3(32, 32)>>>(wq, wk, wv);
    k_xsplit<<<1024, 256>>>(x);
    k_qkv_mma<<<dim3(8, 2, 12), 256, SC_SMEM>>>();
    k_vsum<<<B_ * C_, 256>>>();
    k_score_mma<<<dim3(8, 8, 16), 256, SC_SMEM>>>();
    k_softmax<<<B_ * T_, 256>>>(w_head);
    k_ssq<<<B_ * NH_, 256>>>();
    k_av_mma<<<dim3(8, 16), 256, AV_SMEM>>>(gamma, beta);
    k_proj<<<dim3(16, 4, 4), 256>>>(w_proj, b_proj, out);
}